// round 1
// baseline (speedup 1.0000x reference)
#include <cuda_runtime.h>
#include <cstdint>

#define NN 16000
#define EE 256000
#define ET 272000   // EE + NN self loops
#define BB 32
#define IN_DIM 768
#define HID 256
#define H1 4
#define OUT_DIM 128
#define H2 2
#define D1 (H1*HID)    // 1024
#define D2 (H2*OUT_DIM) // 256
#define LN_EPS 1e-5f

// ---------------- scratch (static device globals; no allocation allowed) ----
__device__ float g_h1pre[(size_t)NN * D1];   // layer1 GEMM out (pre-agg features)
__device__ float g_h1[(size_t)NN * D1];      // layer1 output (post elu)
__device__ float g_t2[(size_t)NN * D2];      // layer2 GEMM out
__device__ float g_as1[NN * H1];
__device__ float g_ad1[NN * H1];
__device__ float g_as2[NN * H2];
__device__ float g_ad2[NN * H2];
__device__ int   g_deg[NN];
__device__ int   g_rowptr[NN + 1];
__device__ int   g_fill[NN];
__device__ int   g_csrc[ET];
__device__ float g_pooled[BB * OUT_DIM];
__device__ int   g_cnt[BB];

__device__ __forceinline__ float lrelu(float x) { return x > 0.f ? x : 0.2f * x; }
__device__ __forceinline__ float elu(float x) { return x > 0.f ? x : expm1f(x); }

// ---------------- init ------------------------------------------------------
__global__ void zero_init_kernel() {
    int i = blockIdx.x * blockDim.x + threadIdx.x;
    if (i < NN) { g_deg[i] = 0; g_fill[i] = 0; }
    if (i < BB * OUT_DIM) g_pooled[i] = 0.f;
    if (i < BB) g_cnt[i] = 0;
}

// ---------------- SGEMM: C[M,N] = A[M,K] * B[N,K]^T (all row-major, K-contig)
// M%128==0, N%128==0, K%16==0 required.
#define BM 128
#define BN 128
#define BK 16
__global__ __launch_bounds__(256) void sgemm_nt(
    const float* __restrict__ A, const float* __restrict__ B,
    float* __restrict__ C, int M, int N, int K)
{
    __shared__ float As[BK][BM];
    __shared__ float Bs[BK][BN];
    int tid = threadIdx.x;
    int bm = blockIdx.y * BM;
    int bn = blockIdx.x * BN;

    // load mapping: each thread loads 2 float4 from A-tile and 2 from B-tile
    int lrow = tid >> 2;          // 0..63
    int lk   = (tid & 3) * 4;     // 0,4,8,12

    int tx = tid & 15;            // 0..15 -> 8 cols each
    int ty = tid >> 4;            // 0..15 -> 8 rows each

    float acc[8][8];
#pragma unroll
    for (int i = 0; i < 8; i++)
#pragma unroll
        for (int j = 0; j < 8; j++) acc[i][j] = 0.f;

    for (int k0 = 0; k0 < K; k0 += BK) {
#pragma unroll
        for (int it = 0; it < 2; it++) {
            int r = lrow + it * 64;
            float4 va = *(const float4*)(A + (size_t)(bm + r) * K + k0 + lk);
            As[lk + 0][r] = va.x; As[lk + 1][r] = va.y;
            As[lk + 2][r] = va.z; As[lk + 3][r] = va.w;
            float4 vb = *(const float4*)(B + (size_t)(bn + r) * K + k0 + lk);
            Bs[lk + 0][r] = vb.x; Bs[lk + 1][r] = vb.y;
            Bs[lk + 2][r] = vb.z; Bs[lk + 3][r] = vb.w;
        }
        __syncthreads();
#pragma unroll
        for (int kk = 0; kk < BK; kk++) {
            float ra[8], rb[8];
#pragma unroll
            for (int i = 0; i < 8; i++) ra[i] = As[kk][ty * 8 + i];
#pragma unroll
            for (int j = 0; j < 8; j++) rb[j] = Bs[kk][tx * 8 + j];
#pragma unroll
            for (int i = 0; i < 8; i++)
#pragma unroll
                for (int j = 0; j < 8; j++)
                    acc[i][j] = fmaf(ra[i], rb[j], acc[i][j]);
        }
        __syncthreads();
    }
#pragma unroll
    for (int i = 0; i < 8; i++) {
        float* c = C + (size_t)(bm + ty * 8 + i) * N + bn + tx * 8;
#pragma unroll
        for (int j = 0; j < 8; j += 4) {
            float4 v = make_float4(acc[i][j], acc[i][j + 1], acc[i][j + 2], acc[i][j + 3]);
            *(float4*)(c + j) = v;
        }
    }
}

// ---------------- alpha projections ----------------------------------------
// layer1: block 128 = 4 warps, warp w handles head w (HID=256)
__global__ void alpha1_kernel(const float* __restrict__ h,
                              const float* __restrict__ a_src,
                              const float* __restrict__ a_dst)
{
    int n = blockIdx.x;
    int w = threadIdx.x >> 5, lane = threadIdx.x & 31;
    const float* row = h + (size_t)n * D1 + w * HID;
    float ss = 0.f, sd = 0.f;
#pragma unroll
    for (int o = lane; o < HID; o += 32) {
        float v = row[o];
        ss = fmaf(v, a_src[w * HID + o], ss);
        sd = fmaf(v, a_dst[w * HID + o], sd);
    }
#pragma unroll
    for (int off = 16; off; off >>= 1) {
        ss += __shfl_down_sync(0xffffffffu, ss, off);
        sd += __shfl_down_sync(0xffffffffu, sd, off);
    }
    if (lane == 0) { g_as1[n * H1 + w] = ss; g_ad1[n * H1 + w] = sd; }
}

// layer2: block 64 = 2 warps, warp w head w (OUT=128)
__global__ void alpha2_kernel(const float* __restrict__ h,
                              const float* __restrict__ a_src,
                              const float* __restrict__ a_dst)
{
    int n = blockIdx.x;
    int w = threadIdx.x >> 5, lane = threadIdx.x & 31;
    const float* row = h + (size_t)n * D2 + w * OUT_DIM;
    float ss = 0.f, sd = 0.f;
#pragma unroll
    for (int o = lane; o < OUT_DIM; o += 32) {
        float v = row[o];
        ss = fmaf(v, a_src[w * OUT_DIM + o], ss);
        sd = fmaf(v, a_dst[w * OUT_DIM + o], sd);
    }
#pragma unroll
    for (int off = 16; off; off >>= 1) {
        ss += __shfl_down_sync(0xffffffffu, ss, off);
        sd += __shfl_down_sync(0xffffffffu, sd, off);
    }
    if (lane == 0) { g_as2[n * H2 + w] = ss; g_ad2[n * H2 + w] = sd; }
}

// ---------------- CSR build -------------------------------------------------
__global__ void hist_kernel(const int* __restrict__ ei) {
    int e = blockIdx.x * blockDim.x + threadIdx.x;
    if (e >= ET) return;
    int dst = (e < EE) ? ei[EE + e] : (e - EE);
    atomicAdd(&g_deg[dst], 1);
}

__global__ void scan_kernel() {
    __shared__ int sm[1024];
    __shared__ int carry;
    int t = threadIdx.x;
    if (t == 0) { carry = 0; g_rowptr[0] = 0; }
    __syncthreads();
    for (int base = 0; base < NN; base += 1024) {
        int i = base + t;
        int v = (i < NN) ? g_deg[i] : 0;
        sm[t] = v;
        __syncthreads();
        for (int off = 1; off < 1024; off <<= 1) {
            int add = (t >= off) ? sm[t - off] : 0;
            __syncthreads();
            sm[t] += add;
            __syncthreads();
        }
        if (i < NN) g_rowptr[i + 1] = sm[t] + carry;
        __syncthreads();
        if (t == 0) carry += sm[1023];
        __syncthreads();
    }
}

__global__ void scatter_kernel(const int* __restrict__ ei) {
    int e = blockIdx.x * blockDim.x + threadIdx.x;
    if (e >= ET) return;
    int src, dst;
    if (e < EE) { src = ei[e]; dst = ei[EE + e]; }
    else        { src = dst = e - EE; }
    int pos = g_rowptr[dst] + atomicAdd(&g_fill[dst], 1);
    g_csrc[pos] = src;
}

// ---------------- layer1 attention + aggregation (block per node, 256 thr) --
#define CH1 512
__global__ __launch_bounds__(256) void gat1_agg(
    const float* __restrict__ h, const float* __restrict__ b1,
    float* __restrict__ out)
{
    __shared__ float s_ex[CH1 * 4];
    __shared__ int   s_src[CH1];
    __shared__ float s_red[256 * 4];
    int n = blockIdx.x, tid = threadIdx.x;
    int row = g_rowptr[n];
    int deg = g_rowptr[n + 1] - row;
    float4 adv = *(const float4*)(g_ad1 + n * 4);

    // pass A: per-head max of e
    float m0 = -1e30f, m1 = -1e30f, m2 = -1e30f, m3 = -1e30f;
    for (int j = tid; j < deg; j += 256) {
        int s = g_csrc[row + j];
        float4 a = *(const float4*)(g_as1 + s * 4);
        m0 = fmaxf(m0, lrelu(a.x + adv.x));
        m1 = fmaxf(m1, lrelu(a.y + adv.y));
        m2 = fmaxf(m2, lrelu(a.z + adv.z));
        m3 = fmaxf(m3, lrelu(a.w + adv.w));
    }
    s_red[tid] = m0; s_red[256 + tid] = m1; s_red[512 + tid] = m2; s_red[768 + tid] = m3;
    __syncthreads();
    for (int off = 128; off; off >>= 1) {
        if (tid < off) {
#pragma unroll
            for (int hh = 0; hh < 4; hh++)
                s_red[hh * 256 + tid] = fmaxf(s_red[hh * 256 + tid], s_red[hh * 256 + tid + off]);
        }
        __syncthreads();
    }
    m0 = s_red[0]; m1 = s_red[256]; m2 = s_red[512]; m3 = s_red[768];
    __syncthreads();

    // pass B: accumulate exp-weighted features + den (normalize at end)
    float acc0 = 0.f, acc1 = 0.f, acc2 = 0.f, acc3 = 0.f;
    float d0 = 0.f, d1 = 0.f, d2 = 0.f, d3 = 0.f;
    for (int base = 0; base < deg; base += CH1) {
        int cnt = min(CH1, deg - base);
        for (int j = tid; j < cnt; j += 256) {
            int s = g_csrc[row + base + j];
            s_src[j] = s;
            float4 a = *(const float4*)(g_as1 + s * 4);
            float x0 = __expf(lrelu(a.x + adv.x) - m0);
            float x1 = __expf(lrelu(a.y + adv.y) - m1);
            float x2 = __expf(lrelu(a.z + adv.z) - m2);
            float x3 = __expf(lrelu(a.w + adv.w) - m3);
            s_ex[j * 4 + 0] = x0; s_ex[j * 4 + 1] = x1;
            s_ex[j * 4 + 2] = x2; s_ex[j * 4 + 3] = x3;
            d0 += x0; d1 += x1; d2 += x2; d3 += x3;
        }
        __syncthreads();
        for (int j = 0; j < cnt; j++) {
            int s = s_src[j];
            float4 xw = *(const float4*)(s_ex + j * 4);
            const float* hr = h + (size_t)s * D1 + tid;
            acc0 = fmaf(hr[0],   xw.x, acc0);
            acc1 = fmaf(hr[256], xw.y, acc1);
            acc2 = fmaf(hr[512], xw.z, acc2);
            acc3 = fmaf(hr[768], xw.w, acc3);
        }
        __syncthreads();
    }
    // reduce den
    s_red[tid] = d0; s_red[256 + tid] = d1; s_red[512 + tid] = d2; s_red[768 + tid] = d3;
    __syncthreads();
    for (int off = 128; off; off >>= 1) {
        if (tid < off) {
#pragma unroll
            for (int hh = 0; hh < 4; hh++)
                s_red[hh * 256 + tid] += s_red[hh * 256 + tid + off];
        }
        __syncthreads();
    }
    float i0 = 1.f / (s_red[0] + 1e-16f);
    float i1 = 1.f / (s_red[256] + 1e-16f);
    float i2 = 1.f / (s_red[512] + 1e-16f);
    float i3 = 1.f / (s_red[768] + 1e-16f);

    float* o = out + (size_t)n * D1;
    o[tid]       = elu(acc0 * i0 + b1[tid]);
    o[256 + tid] = elu(acc1 * i1 + b1[256 + tid]);
    o[512 + tid] = elu(acc2 * i2 + b1[512 + tid]);
    o[768 + tid] = elu(acc3 * i3 + b1[768 + tid]);
}

// ---------------- layer2 attention + aggregation (block per node, 128 thr) --
#define CH2 512
__global__ __launch_bounds__(128) void gat2_agg(
    const float* __restrict__ h, const float* __restrict__ b2,
    float* __restrict__ h2out)
{
    __shared__ float s_ex[CH2 * 2];
    __shared__ int   s_src[CH2];
    __shared__ float s_red[128 * 2];
    int n = blockIdx.x, tid = threadIdx.x;
    int row = g_rowptr[n];
    int deg = g_rowptr[n + 1] - row;
    float2 adv = *(const float2*)(g_ad2 + n * 2);

    float m0 = -1e30f, m1 = -1e30f;
    for (int j = tid; j < deg; j += 128) {
        int s = g_csrc[row + j];
        float2 a = *(const float2*)(g_as2 + s * 2);
        m0 = fmaxf(m0, lrelu(a.x + adv.x));
        m1 = fmaxf(m1, lrelu(a.y + adv.y));
    }
    s_red[tid] = m0; s_red[128 + tid] = m1;
    __syncthreads();
    for (int off = 64; off; off >>= 1) {
        if (tid < off) {
            s_red[tid] = fmaxf(s_red[tid], s_red[tid + off]);
            s_red[128 + tid] = fmaxf(s_red[128 + tid], s_red[128 + tid + off]);
        }
        __syncthreads();
    }
    m0 = s_red[0]; m1 = s_red[128];
    __syncthreads();

    float acc0 = 0.f, acc1 = 0.f, d0 = 0.f, d1 = 0.f;
    for (int base = 0; base < deg; base += CH2) {
        int cnt = min(CH2, deg - base);
        for (int j = tid; j < cnt; j += 128) {
            int s = g_csrc[row + base + j];
            s_src[j] = s;
            float2 a = *(const float2*)(g_as2 + s * 2);
            float x0 = __expf(lrelu(a.x + adv.x) - m0);
            float x1 = __expf(lrelu(a.y + adv.y) - m1);
            s_ex[j * 2 + 0] = x0; s_ex[j * 2 + 1] = x1;
            d0 += x0; d1 += x1;
        }
        __syncthreads();
        for (int j = 0; j < cnt; j++) {
            int s = s_src[j];
            float2 xw = *(const float2*)(s_ex + j * 2);
            const float* hr = h + (size_t)s * D2 + tid;
            acc0 = fmaf(hr[0],   xw.x, acc0);
            acc1 = fmaf(hr[128], xw.y, acc1);
        }
        __syncthreads();
    }
    s_red[tid] = d0; s_red[128 + tid] = d1;
    __syncthreads();
    for (int off = 64; off; off >>= 1) {
        if (tid < off) {
            s_red[tid] += s_red[tid + off];
            s_red[128 + tid] += s_red[128 + tid + off];
        }
        __syncthreads();
    }
    float i0 = 1.f / (s_red[0] + 1e-16f);
    float i1 = 1.f / (s_red[128] + 1e-16f);
    float o = (acc0 * i0 + acc1 * i1) * 0.5f + b2[tid];
    h2out[(size_t)n * OUT_DIM + tid] = elu(o);
}

// ---------------- pooling ---------------------------------------------------
__global__ void pool_kernel(const float* __restrict__ h2, const int* __restrict__ batch) {
    int n = blockIdx.x, t = threadIdx.x;
    int b = batch[n];
    atomicAdd(&g_pooled[b * OUT_DIM + t], h2[(size_t)n * OUT_DIM + t]);
    if (t == 0) atomicAdd(&g_cnt[b], 1);
}

// ---------------- proj + layernorm (block per graph, 768 threads) -----------
__global__ __launch_bounds__(768) void proj_ln_kernel(
    const float* __restrict__ W, const float* __restrict__ pb,
    const float* __restrict__ g, const float* __restrict__ beta,
    float* __restrict__ out)
{
    __shared__ float sp[OUT_DIM];
    __shared__ float red[768];
    int b = blockIdx.x, j = threadIdx.x;
    float c = (float)max(g_cnt[b], 1);
    if (j < OUT_DIM) sp[j] = g_pooled[b * OUT_DIM + j] / c;
    __syncthreads();
    float z = pb[j];
    const float* w = W + (size_t)j * OUT_DIM;
#pragma unroll 8
    for (int k = 0; k < OUT_DIM; k++) z = fmaf(sp[k], w[k], z);

    // mean
    red[j] = z; __syncthreads();
    if (j < 256) red[j] += red[j + 512];
    __syncthreads();
    if (j < 256) red[j] += red[j + 256];
    __syncthreads();
    for (int off = 128; off; off >>= 1) { if (j < off) red[j] += red[j + off]; __syncthreads(); }
    float mean = red[0] / 768.f;
    __syncthreads();
    float dz = z - mean;
    red[j] = dz * dz; __syncthreads();
    if (j < 256) red[j] += red[j + 512];
    __syncthreads();
    if (j < 256) red[j] += red[j + 256];
    __syncthreads();
    for (int off = 128; off; off >>= 1) { if (j < off) red[j] += red[j + off]; __syncthreads(); }
    float var = red[0] / 768.f;
    out[(size_t)b * 768 + j] = dz * rsqrtf(var + LN_EPS) * g[j] + beta[j];
}

// ---------------- launch ----------------------------------------------------
extern "C" void kernel_launch(void* const* d_in, const int* in_sizes, int n_in,
                              void* d_out, int out_size)
{
    const float* x   = (const float*)d_in[0];
    const int*   ei  = (const int*)  d_in[1];
    const int*   bat = (const int*)  d_in[2];
    const float* W1  = (const float*)d_in[3];
    const float* a1s = (const float*)d_in[4];
    const float* a1d = (const float*)d_in[5];
    const float* b1  = (const float*)d_in[6];
    const float* W2  = (const float*)d_in[7];
    const float* a2s = (const float*)d_in[8];
    const float* a2d = (const float*)d_in[9];
    const float* b2  = (const float*)d_in[10];
    const float* pW  = (const float*)d_in[11];
    const float* pb  = (const float*)d_in[12];
    const float* lg  = (const float*)d_in[13];
    const float* lb  = (const float*)d_in[14];

    float* out = (float*)d_out;
    float* ge  = out;                 // (32, 768)
    float* h2  = out + BB * 768;      // (16000, 128)

    float *h1pre, *h1, *t2;
    cudaGetSymbolAddress((void**)&h1pre, g_h1pre);
    cudaGetSymbolAddress((void**)&h1, g_h1);
    cudaGetSymbolAddress((void**)&t2, g_t2);

    zero_init_kernel<<<(NN + 255) / 256, 256>>>();

    // CSR build (independent of GEMM; interleave for overlap later rounds)
    hist_kernel<<<(ET + 255) / 256, 256>>>(ei);
    scan_kernel<<<1, 1024>>>();
    scatter_kernel<<<(ET + 255) / 256, 256>>>(ei);

    // layer 1
    {
        dim3 grid(D1 / BN, NN / BM);
        sgemm_nt<<<grid, 256>>>(x, W1, h1pre, NN, D1, IN_DIM);
    }
    alpha1_kernel<<<NN, 128>>>(h1pre, a1s, a1d);
    gat1_agg<<<NN, 256>>>(h1pre, b1, h1);

    // layer 2
    {
        dim3 grid(D2 / BN, NN / BM);
        sgemm_nt<<<grid, 256>>>(h1, W2, t2, NN, D2, D1);
    }
    alpha2_kernel<<<NN, 64>>>(t2, a2s, a2d);
    gat2_agg<<<NN, 128>>>(t2, b2, h2);

    // pool + proj + LN
    pool_kernel<<<NN, OUT_DIM>>>(h2, bat);
    proj_ln_kernel<<<BB, 768>>>(pW, pb, lg, lb, ge);
}

// round 2
// speedup vs baseline: 1.8584x; 1.8584x over previous
#include <cuda_runtime.h>
#include <cstdint>

#define NN 16000
#define EE 256000
#define ET 272000   // EE + NN self loops
#define BB 32
#define IN_DIM 768
#define HID 256
#define H1 4
#define OUT_DIM 128
#define H2 2
#define D1 (H1*HID)    // 1024
#define D2 (H2*OUT_DIM) // 256
#define LN_EPS 1e-5f

// ---------------- scratch (static device globals; no allocation allowed) ----
__device__ float g_h1pre[(size_t)NN * D1];   // layer1 GEMM out (pre-agg features)
__device__ float g_h1[(size_t)NN * D1];      // layer1 output (post elu)
__device__ float g_t2[(size_t)NN * D2];      // layer2 GEMM out
__device__ float g_as1[NN * H1];
__device__ float g_ad1[NN * H1];
__device__ float g_as2[NN * H2];
__device__ float g_ad2[NN * H2];
__device__ int   g_deg[NN];
__device__ int   g_rowptr[NN + 1];
__device__ int   g_fill[NN];
__device__ int   g_csrc[ET];
__device__ float g_pooled[BB * OUT_DIM];
__device__ int   g_cnt[BB];

__device__ __forceinline__ float lrelu(float x) { return x > 0.f ? x : 0.2f * x; }
__device__ __forceinline__ float elu(float x) { return x > 0.f ? x : expm1f(x); }

__device__ __forceinline__ uint32_t to_tf32(float f) {
    uint32_t o;
    asm("cvt.rna.tf32.f32 %0, %1;" : "=r"(o) : "f"(f));
    return o;
}

// ---------------- init ------------------------------------------------------
__global__ void zero_init_kernel() {
    int i = blockIdx.x * blockDim.x + threadIdx.x;
    if (i < NN) { g_deg[i] = 0; g_fill[i] = 0; }
    if (i < BB * OUT_DIM) g_pooled[i] = 0.f;
    if (i < BB) g_cnt[i] = 0;
}

// ---------------- TF32 tensor-core GEMM: C[M,N] = A[M,K] * B[N,K]^T ---------
// Row-major A (M,K), B (N,K). M%128==0, N%256==0, K%16==0.
// Block tile 128x256, BK=16, 8 warps of 64x64, double-buffered swizzled smem.
#define TBM 128
#define TBN 256
#define TBK 16
#define SA_STRIDE 136   // %32 == 8 -> conflict-free frag loads
#define SB_STRIDE 264   // %32 == 8
#define SA_BUF (TBK * SA_STRIDE)   // 2176 u32
#define SB_BUF (TBK * SB_STRIDE)   // 4224 u32
#define SMEM_U32 (2 * SA_BUF + 2 * SB_BUF)  // 12800 u32 = 51200 B

__global__ __launch_bounds__(256, 1) void sgemm_tf32(
    const float* __restrict__ A, const float* __restrict__ B,
    float* __restrict__ C, int M, int N, int K)
{
    extern __shared__ uint32_t smem[];
    uint32_t* sA = smem;                 // [2][TBK][SA_STRIDE]
    uint32_t* sB = smem + 2 * SA_BUF;    // [2][TBK][SB_STRIDE]

    const int tid  = threadIdx.x;
    const int lane = tid & 31;
    const int wid  = tid >> 5;
    const int g    = lane >> 2;       // 0..7
    const int tig  = lane & 3;        // 0..3
    const int wm   = wid >> 2;        // 0..1
    const int wn   = wid & 3;         // 0..3
    const int bm   = blockIdx.y * TBM;
    const int bn   = blockIdx.x * TBN;

    // loader mapping (both A and B): c = k-chunk (float4), row = tile row
    const int lc   = tid & 3;         // 0..3 -> k offset lc*4
    const int lrow = tid >> 2;        // 0..63

    const float* Ag = A + (size_t)(bm + lrow) * K + lc * 4;
    const float* Bg = B + (size_t)(bn + lrow) * K + lc * 4;

    float acc[4][8][4];
#pragma unroll
    for (int mt = 0; mt < 4; mt++)
#pragma unroll
        for (int nt = 0; nt < 8; nt++)
#pragma unroll
            for (int i = 0; i < 4; i++) acc[mt][nt][i] = 0.f;

    float4 ra[2], rb[4];

    // prologue: global load tile k0=0
#pragma unroll
    for (int it = 0; it < 2; it++) ra[it] = *(const float4*)(Ag + (size_t)it * 64 * K);
#pragma unroll
    for (int it = 0; it < 4; it++) rb[it] = *(const float4*)(Bg + (size_t)it * 64 * K);

    const int swz = lc << 3;  // xor-swizzle constant for this loader's k-chunk

    // store staged regs into smem buffer 'buf'
    auto store_tile = [&](int buf) {
        uint32_t* pa = sA + buf * SA_BUF;
        uint32_t* pb = sB + buf * SB_BUF;
#pragma unroll
        for (int it = 0; it < 2; it++) {
            int row = lrow + it * 64;
            const float* v = (const float*)&ra[it];
#pragma unroll
            for (int i = 0; i < 4; i++)
                pa[(lc * 4 + i) * SA_STRIDE + (row ^ swz)] = to_tf32(v[i]);
        }
#pragma unroll
        for (int it = 0; it < 4; it++) {
            int row = lrow + it * 64;
            const float* v = (const float*)&rb[it];
#pragma unroll
            for (int i = 0; i < 4; i++)
                pb[(lc * 4 + i) * SB_STRIDE + (row ^ swz)] = to_tf32(v[i]);
        }
    };

    store_tile(0);
    __syncthreads();

    int buf = 0;
    for (int k0 = 0; k0 < K; k0 += TBK) {
        const bool has_next = (k0 + TBK) < K;
        if (has_next) {
            const float* Agn = Ag + k0 + TBK;
            const float* Bgn = Bg + k0 + TBK;
#pragma unroll
            for (int it = 0; it < 2; it++) ra[it] = *(const float4*)(Agn + (size_t)it * 64 * K);
#pragma unroll
            for (int it = 0; it < 4; it++) rb[it] = *(const float4*)(Bgn + (size_t)it * 64 * K);
        }

        const uint32_t* pa = sA + buf * SA_BUF;
        const uint32_t* pb = sB + buf * SB_BUF;
#pragma unroll
        for (int ks = 0; ks < TBK; ks += 8) {
            const int kk = ks + tig;            // frag k for a0/a1/b0
            const int C0 = ((kk >> 2) & 3) << 3;        // swizzle for k row kk
            const int C1 = (((kk + 4) >> 2) & 3) << 3;  // for k row kk+4

            uint32_t af[4][4];
#pragma unroll
            for (int mt = 0; mt < 4; mt++) {
                int m = wm * 64 + mt * 16 + g;
                af[mt][0] = pa[kk * SA_STRIDE + (m ^ C0)];
                af[mt][1] = pa[kk * SA_STRIDE + ((m + 8) ^ C0)];
                af[mt][2] = pa[(kk + 4) * SA_STRIDE + (m ^ C1)];
                af[mt][3] = pa[(kk + 4) * SA_STRIDE + ((m + 8) ^ C1)];
            }
            uint32_t bf[8][2];
#pragma unroll
            for (int nt = 0; nt < 8; nt++) {
                int n = wn * 64 + nt * 8 + g;
                bf[nt][0] = pb[kk * SB_STRIDE + (n ^ C0)];
                bf[nt][1] = pb[(kk + 4) * SB_STRIDE + (n ^ C1)];
            }
#pragma unroll
            for (int mt = 0; mt < 4; mt++)
#pragma unroll
                for (int nt = 0; nt < 8; nt++) {
                    asm volatile(
                        "mma.sync.aligned.m16n8k8.row.col.f32.tf32.tf32.f32 "
                        "{%0,%1,%2,%3}, {%4,%5,%6,%7}, {%8,%9}, {%0,%1,%2,%3};"
                        : "+f"(acc[mt][nt][0]), "+f"(acc[mt][nt][1]),
                          "+f"(acc[mt][nt][2]), "+f"(acc[mt][nt][3])
                        : "r"(af[mt][0]), "r"(af[mt][1]), "r"(af[mt][2]), "r"(af[mt][3]),
                          "r"(bf[nt][0]), "r"(bf[nt][1]));
                }
        }

        if (has_next) store_tile(buf ^ 1);
        __syncthreads();
        buf ^= 1;
    }

    // epilogue
#pragma unroll
    for (int mt = 0; mt < 4; mt++) {
        int r0 = bm + wm * 64 + mt * 16 + g;
#pragma unroll
        for (int nt = 0; nt < 8; nt++) {
            int cc = bn + wn * 64 + nt * 8 + tig * 2;
            float2 v0 = make_float2(acc[mt][nt][0], acc[mt][nt][1]);
            float2 v1 = make_float2(acc[mt][nt][2], acc[mt][nt][3]);
            *(float2*)(C + (size_t)r0 * N + cc) = v0;
            *(float2*)(C + (size_t)(r0 + 8) * N + cc) = v1;
        }
    }
}

// ---------------- alpha projections ----------------------------------------
__global__ void alpha1_kernel(const float* __restrict__ h,
                              const float* __restrict__ a_src,
                              const float* __restrict__ a_dst)
{
    int n = blockIdx.x;
    int w = threadIdx.x >> 5, lane = threadIdx.x & 31;
    const float* row = h + (size_t)n * D1 + w * HID;
    float ss = 0.f, sd = 0.f;
#pragma unroll
    for (int o = lane; o < HID; o += 32) {
        float v = row[o];
        ss = fmaf(v, a_src[w * HID + o], ss);
        sd = fmaf(v, a_dst[w * HID + o], sd);
    }
#pragma unroll
    for (int off = 16; off; off >>= 1) {
        ss += __shfl_down_sync(0xffffffffu, ss, off);
        sd += __shfl_down_sync(0xffffffffu, sd, off);
    }
    if (lane == 0) { g_as1[n * H1 + w] = ss; g_ad1[n * H1 + w] = sd; }
}

__global__ void alpha2_kernel(const float* __restrict__ h,
                              const float* __restrict__ a_src,
                              const float* __restrict__ a_dst)
{
    int n = blockIdx.x;
    int w = threadIdx.x >> 5, lane = threadIdx.x & 31;
    const float* row = h + (size_t)n * D2 + w * OUT_DIM;
    float ss = 0.f, sd = 0.f;
#pragma unroll
    for (int o = lane; o < OUT_DIM; o += 32) {
        float v = row[o];
        ss = fmaf(v, a_src[w * OUT_DIM + o], ss);
        sd = fmaf(v, a_dst[w * OUT_DIM + o], sd);
    }
#pragma unroll
    for (int off = 16; off; off >>= 1) {
        ss += __shfl_down_sync(0xffffffffu, ss, off);
        sd += __shfl_down_sync(0xffffffffu, sd, off);
    }
    if (lane == 0) { g_as2[n * H2 + w] = ss; g_ad2[n * H2 + w] = sd; }
}

// ---------------- CSR build -------------------------------------------------
__global__ void hist_kernel(const int* __restrict__ ei) {
    int e = blockIdx.x * blockDim.x + threadIdx.x;
    if (e >= ET) return;
    int dst = (e < EE) ? ei[EE + e] : (e - EE);
    atomicAdd(&g_deg[dst], 1);
}

__global__ void scan_kernel() {
    __shared__ int sm[1024];
    __shared__ int carry;
    int t = threadIdx.x;
    if (t == 0) { carry = 0; g_rowptr[0] = 0; }
    __syncthreads();
    for (int base = 0; base < NN; base += 1024) {
        int i = base + t;
        int v = (i < NN) ? g_deg[i] : 0;
        sm[t] = v;
        __syncthreads();
        for (int off = 1; off < 1024; off <<= 1) {
            int add = (t >= off) ? sm[t - off] : 0;
            __syncthreads();
            sm[t] += add;
            __syncthreads();
        }
        if (i < NN) g_rowptr[i + 1] = sm[t] + carry;
        __syncthreads();
        if (t == 0) carry += sm[1023];
        __syncthreads();
    }
}

__global__ void scatter_kernel(const int* __restrict__ ei) {
    int e = blockIdx.x * blockDim.x + threadIdx.x;
    if (e >= ET) return;
    int src, dst;
    if (e < EE) { src = ei[e]; dst = ei[EE + e]; }
    else        { src = dst = e - EE; }
    int pos = g_rowptr[dst] + atomicAdd(&g_fill[dst], 1);
    g_csrc[pos] = src;
}

// ---------------- layer1 attention + aggregation (block per node, 256 thr) --
#define CH1 512
__global__ __launch_bounds__(256) void gat1_agg(
    const float* __restrict__ h, const float* __restrict__ b1,
    float* __restrict__ out)
{
    __shared__ float s_ex[CH1 * 4];
    __shared__ int   s_src[CH1];
    __shared__ float s_red[256 * 4];
    int n = blockIdx.x, tid = threadIdx.x;
    int row = g_rowptr[n];
    int deg = g_rowptr[n + 1] - row;
    float4 adv = *(const float4*)(g_ad1 + n * 4);

    float m0 = -1e30f, m1 = -1e30f, m2 = -1e30f, m3 = -1e30f;
    for (int j = tid; j < deg; j += 256) {
        int s = g_csrc[row + j];
        float4 a = *(const float4*)(g_as1 + s * 4);
        m0 = fmaxf(m0, lrelu(a.x + adv.x));
        m1 = fmaxf(m1, lrelu(a.y + adv.y));
        m2 = fmaxf(m2, lrelu(a.z + adv.z));
        m3 = fmaxf(m3, lrelu(a.w + adv.w));
    }
    s_red[tid] = m0; s_red[256 + tid] = m1; s_red[512 + tid] = m2; s_red[768 + tid] = m3;
    __syncthreads();
    for (int off = 128; off; off >>= 1) {
        if (tid < off) {
#pragma unroll
            for (int hh = 0; hh < 4; hh++)
                s_red[hh * 256 + tid] = fmaxf(s_red[hh * 256 + tid], s_red[hh * 256 + tid + off]);
        }
        __syncthreads();
    }
    m0 = s_red[0]; m1 = s_red[256]; m2 = s_red[512]; m3 = s_red[768];
    __syncthreads();

    float acc0 = 0.f, acc1 = 0.f, acc2 = 0.f, acc3 = 0.f;
    float d0 = 0.f, d1 = 0.f, d2 = 0.f, d3 = 0.f;
    for (int base = 0; base < deg; base += CH1) {
        int cnt = min(CH1, deg - base);
        for (int j = tid; j < cnt; j += 256) {
            int s = g_csrc[row + base + j];
            s_src[j] = s;
            float4 a = *(const float4*)(g_as1 + s * 4);
            float x0 = __expf(lrelu(a.x + adv.x) - m0);
            float x1 = __expf(lrelu(a.y + adv.y) - m1);
            float x2 = __expf(lrelu(a.z + adv.z) - m2);
            float x3 = __expf(lrelu(a.w + adv.w) - m3);
            s_ex[j * 4 + 0] = x0; s_ex[j * 4 + 1] = x1;
            s_ex[j * 4 + 2] = x2; s_ex[j * 4 + 3] = x3;
            d0 += x0; d1 += x1; d2 += x2; d3 += x3;
        }
        __syncthreads();
        for (int j = 0; j < cnt; j++) {
            int s = s_src[j];
            float4 xw = *(const float4*)(s_ex + j * 4);
            const float* hr = h + (size_t)s * D1 + tid;
            acc0 = fmaf(hr[0],   xw.x, acc0);
            acc1 = fmaf(hr[256], xw.y, acc1);
            acc2 = fmaf(hr[512], xw.z, acc2);
            acc3 = fmaf(hr[768], xw.w, acc3);
        }
        __syncthreads();
    }
    s_red[tid] = d0; s_red[256 + tid] = d1; s_red[512 + tid] = d2; s_red[768 + tid] = d3;
    __syncthreads();
    for (int off = 128; off; off >>= 1) {
        if (tid < off) {
#pragma unroll
            for (int hh = 0; hh < 4; hh++)
                s_red[hh * 256 + tid] += s_red[hh * 256 + tid + off];
        }
        __syncthreads();
    }
    float i0 = 1.f / (s_red[0] + 1e-16f);
    float i1 = 1.f / (s_red[256] + 1e-16f);
    float i2 = 1.f / (s_red[512] + 1e-16f);
    float i3 = 1.f / (s_red[768] + 1e-16f);

    float* o = out + (size_t)n * D1;
    o[tid]       = elu(acc0 * i0 + b1[tid]);
    o[256 + tid] = elu(acc1 * i1 + b1[256 + tid]);
    o[512 + tid] = elu(acc2 * i2 + b1[512 + tid]);
    o[768 + tid] = elu(acc3 * i3 + b1[768 + tid]);
}

// ---------------- layer2 attention + aggregation (block per node, 128 thr) --
#define CH2 512
__global__ __launch_bounds__(128) void gat2_agg(
    const float* __restrict__ h, const float* __restrict__ b2,
    float* __restrict__ h2out)
{
    __shared__ float s_ex[CH2 * 2];
    __shared__ int   s_src[CH2];
    __shared__ float s_red[128 * 2];
    int n = blockIdx.x, tid = threadIdx.x;
    int row = g_rowptr[n];
    int deg = g_rowptr[n + 1] - row;
    float2 adv = *(const float2*)(g_ad2 + n * 2);

    float m0 = -1e30f, m1 = -1e30f;
    for (int j = tid; j < deg; j += 128) {
        int s = g_csrc[row + j];
        float2 a = *(const float2*)(g_as2 + s * 2);
        m0 = fmaxf(m0, lrelu(a.x + adv.x));
        m1 = fmaxf(m1, lrelu(a.y + adv.y));
    }
    s_red[tid] = m0; s_red[128 + tid] = m1;
    __syncthreads();
    for (int off = 64; off; off >>= 1) {
        if (tid < off) {
            s_red[tid] = fmaxf(s_red[tid], s_red[tid + off]);
            s_red[128 + tid] = fmaxf(s_red[128 + tid], s_red[128 + tid + off]);
        }
        __syncthreads();
    }
    m0 = s_red[0]; m1 = s_red[128];
    __syncthreads();

    float acc0 = 0.f, acc1 = 0.f, d0 = 0.f, d1 = 0.f;
    for (int base = 0; base < deg; base += CH2) {
        int cnt = min(CH2, deg - base);
        for (int j = tid; j < cnt; j += 128) {
            int s = g_csrc[row + base + j];
            s_src[j] = s;
            float2 a = *(const float2*)(g_as2 + s * 2);
            float x0 = __expf(lrelu(a.x + adv.x) - m0);
            float x1 = __expf(lrelu(a.y + adv.y) - m1);
            s_ex[j * 2 + 0] = x0; s_ex[j * 2 + 1] = x1;
            d0 += x0; d1 += x1;
        }
        __syncthreads();
        for (int j = 0; j < cnt; j++) {
            int s = s_src[j];
            float2 xw = *(const float2*)(s_ex + j * 2);
            const float* hr = h + (size_t)s * D2 + tid;
            acc0 = fmaf(hr[0],   xw.x, acc0);
            acc1 = fmaf(hr[128], xw.y, acc1);
        }
        __syncthreads();
    }
    s_red[tid] = d0; s_red[128 + tid] = d1;
    __syncthreads();
    for (int off = 64; off; off >>= 1) {
        if (tid < off) {
            s_red[tid] += s_red[tid + off];
            s_red[128 + tid] += s_red[128 + tid + off];
        }
        __syncthreads();
    }
    float i0 = 1.f / (s_red[0] + 1e-16f);
    float i1 = 1.f / (s_red[128] + 1e-16f);
    float o = (acc0 * i0 + acc1 * i1) * 0.5f + b2[tid];
    h2out[(size_t)n * OUT_DIM + tid] = elu(o);
}

// ---------------- pooling ---------------------------------------------------
__global__ void pool_kernel(const float* __restrict__ h2, const int* __restrict__ batch) {
    int n = blockIdx.x, t = threadIdx.x;
    int b = batch[n];
    atomicAdd(&g_pooled[b * OUT_DIM + t], h2[(size_t)n * OUT_DIM + t]);
    if (t == 0) atomicAdd(&g_cnt[b], 1);
}

// ---------------- proj + layernorm (block per graph, 768 threads) -----------
__global__ __launch_bounds__(768) void proj_ln_kernel(
    const float* __restrict__ W, const float* __restrict__ pb,
    const float* __restrict__ g, const float* __restrict__ beta,
    float* __restrict__ out)
{
    __shared__ float sp[OUT_DIM];
    __shared__ float red[768];
    int b = blockIdx.x, j = threadIdx.x;
    float c = (float)max(g_cnt[b], 1);
    if (j < OUT_DIM) sp[j] = g_pooled[b * OUT_DIM + j] / c;
    __syncthreads();
    float z = pb[j];
    const float* w = W + (size_t)j * OUT_DIM;
#pragma unroll 8
    for (int k = 0; k < OUT_DIM; k++) z = fmaf(sp[k], w[k], z);

    red[j] = z; __syncthreads();
    if (j < 256) red[j] += red[j + 512];
    __syncthreads();
    if (j < 256) red[j] += red[j + 256];
    __syncthreads();
    for (int off = 128; off; off >>= 1) { if (j < off) red[j] += red[j + off]; __syncthreads(); }
    float mean = red[0] / 768.f;
    __syncthreads();
    float dz = z - mean;
    red[j] = dz * dz; __syncthreads();
    if (j < 256) red[j] += red[j + 512];
    __syncthreads();
    if (j < 256) red[j] += red[j + 256];
    __syncthreads();
    for (int off = 128; off; off >>= 1) { if (j < off) red[j] += red[j + off]; __syncthreads(); }
    float var = red[0] / 768.f;
    out[(size_t)b * 768 + j] = dz * rsqrtf(var + LN_EPS) * g[j] + beta[j];
}

// ---------------- launch ----------------------------------------------------
extern "C" void kernel_launch(void* const* d_in, const int* in_sizes, int n_in,
                              void* d_out, int out_size)
{
    const float* x   = (const float*)d_in[0];
    const int*   ei  = (const int*)  d_in[1];
    const int*   bat = (const int*)  d_in[2];
    const float* W1  = (const float*)d_in[3];
    const float* a1s = (const float*)d_in[4];
    const float* a1d = (const float*)d_in[5];
    const float* b1  = (const float*)d_in[6];
    const float* W2  = (const float*)d_in[7];
    const float* a2s = (const float*)d_in[8];
    const float* a2d = (const float*)d_in[9];
    const float* b2  = (const float*)d_in[10];
    const float* pW  = (const float*)d_in[11];
    const float* pb  = (const float*)d_in[12];
    const float* lg  = (const float*)d_in[13];
    const float* lb  = (const float*)d_in[14];

    float* out = (float*)d_out;
    float* ge  = out;                 // (32, 768)
    float* h2  = out + BB * 768;      // (16000, 128)

    float *h1pre, *h1, *t2;
    cudaGetSymbolAddress((void**)&h1pre, g_h1pre);
    cudaGetSymbolAddress((void**)&h1, g_h1);
    cudaGetSymbolAddress((void**)&t2, g_t2);

    cudaFuncSetAttribute(sgemm_tf32, cudaFuncAttributeMaxDynamicSharedMemorySize,
                         SMEM_U32 * 4);

    zero_init_kernel<<<(NN + 255) / 256, 256>>>();

    // CSR build
    hist_kernel<<<(ET + 255) / 256, 256>>>(ei);
    scan_kernel<<<1, 1024>>>();
    scatter_kernel<<<(ET + 255) / 256, 256>>>(ei);

    // layer 1: GEMM (16000 x 1024 x 768)
    {
        dim3 grid(D1 / TBN, NN / TBM);   // (4, 125)
        sgemm_tf32<<<grid, 256, SMEM_U32 * 4>>>(x, W1, h1pre, NN, D1, IN_DIM);
    }
    alpha1_kernel<<<NN, 128>>>(h1pre, a1s, a1d);
    gat1_agg<<<NN, 256>>>(h1pre, b1, h1);

    // layer 2: GEMM (16000 x 256 x 1024)
    {
        dim3 grid(D2 / TBN, NN / TBM);   // (1, 125)
        sgemm_tf32<<<grid, 256, SMEM_U32 * 4>>>(h1, W2, t2, NN, D2, D1);
    }
    alpha2_kernel<<<NN, 64>>>(t2, a2s, a2d);
    gat2_agg<<<NN, 128>>>(t2, b2, h2);

    // pool + proj + LN
    pool_kernel<<<NN, OUT_DIM>>>(h2, bat);
    proj_ln_kernel<<<BB, 768>>>(pW, pb, lg, lb, ge);
}

// round 3
// speedup vs baseline: 2.1112x; 1.1360x over previous
#include <cuda_runtime.h>
#include <cstdint>

#define NN 16000
#define EE 256000
#define ET 272000   // EE + NN self loops
#define BB 32
#define IN_DIM 768
#define HID 256
#define H1 4
#define OUT_DIM 128
#define H2 2
#define D1 (H1*HID)    // 1024
#define D2 (H2*OUT_DIM) // 256
#define LN_EPS 1e-5f

// ---------------- scratch (static device globals; no allocation allowed) ----
__device__ float g_xr[(size_t)NN * IN_DIM];  // tf32-rounded x
__device__ float g_w1r[D1 * IN_DIM];         // tf32-rounded W1
__device__ float g_w2r[D2 * D1];             // tf32-rounded W2
__device__ float g_h1pre[(size_t)NN * D1];   // layer1 GEMM out
__device__ float g_h1[(size_t)NN * D1];      // layer1 output (elu, tf32-rounded)
__device__ float g_t2[(size_t)NN * D2];      // layer2 GEMM out
__device__ float g_as1[NN * H1];
__device__ float g_ad1[NN * H1];
__device__ float g_as2[NN * H2];
__device__ float g_ad2[NN * H2];
__device__ int   g_deg[NN];
__device__ int   g_rowptr[NN + 1];
__device__ int   g_fill[NN];
__device__ int   g_csrc[ET];
__device__ float g_pooled[BB * OUT_DIM];
__device__ int   g_cnt[BB];

__device__ __forceinline__ float lrelu(float x) { return x > 0.f ? x : 0.2f * x; }
__device__ __forceinline__ float elu(float x) { return x > 0.f ? x : expm1f(x); }

__device__ __forceinline__ float tf32r(float f) {
    uint32_t o;
    asm("cvt.rna.tf32.f32 %0, %1;" : "=r"(o) : "f"(f));
    return __uint_as_float(o);
}

// ---------------- pre-rounding passes ---------------------------------------
__global__ void round_x_kernel(const float* __restrict__ x) {
    int i = blockIdx.x * blockDim.x + threadIdx.x;
    const int total = NN * IN_DIM / 4;
    if (i >= total) return;
    float4 v = ((const float4*)x)[i];
    v.x = tf32r(v.x); v.y = tf32r(v.y); v.z = tf32r(v.z); v.w = tf32r(v.w);
    ((float4*)g_xr)[i] = v;
}

__global__ void round_w_kernel(const float* __restrict__ W1, const float* __restrict__ W2) {
    int i = blockIdx.x * blockDim.x + threadIdx.x;
    const int n1 = D1 * IN_DIM / 4;
    const int n2 = D2 * D1 / 4;
    if (i < n1) {
        float4 v = ((const float4*)W1)[i];
        v.x = tf32r(v.x); v.y = tf32r(v.y); v.z = tf32r(v.z); v.w = tf32r(v.w);
        ((float4*)g_w1r)[i] = v;
    }
    if (i < n2) {
        float4 v = ((const float4*)W2)[i];
        v.x = tf32r(v.x); v.y = tf32r(v.y); v.z = tf32r(v.z); v.w = tf32r(v.w);
        ((float4*)g_w2r)[i] = v;
    }
}

// ---------------- init ------------------------------------------------------
__global__ void zero_init_kernel() {
    int i = blockIdx.x * blockDim.x + threadIdx.x;
    if (i < NN) { g_deg[i] = 0; g_fill[i] = 0; }
    if (i < BB * OUT_DIM) g_pooled[i] = 0.f;
    if (i < BB) g_cnt[i] = 0;
}

// ---------------- TF32 tensor-core GEMM (cp.async 4-stage pipeline) ---------
// C[M,N] = A[M,K] * B[N,K]^T ; A,B row-major, already tf32-rounded.
// M%128==0, N%256==0, K%16==0. Block tile 128x256x16, 8 warps of 64x64.
#define TBM 128
#define TBN 256
#define TBK 16
#define A_BYTES (TBM * 64)           // 8192  (64B per row = 16 k-floats)
#define B_BYTES (TBN * 64)           // 16384
#define STAGE_BYTES (A_BYTES + B_BYTES)  // 24576
#define NSTAGE 4
#define SMEM_BYTES (NSTAGE * STAGE_BYTES) // 98304

// swizzled word index within a tile: row r (m or n), k index kk (0..15)
// 64B rows; 16B chunk kc = kk>>2 xored with (r ^ (r>>2)) & 3  -> conflict-free
__device__ __forceinline__ int sw_of(int r) { return (r ^ (r >> 2)) & 3; }

__global__ __launch_bounds__(256, 1) void sgemm_tf32(
    const float* __restrict__ A, const float* __restrict__ B,
    float* __restrict__ C, int M, int N, int K)
{
    extern __shared__ uint32_t smem[];
    const uint32_t smem_base = (uint32_t)__cvta_generic_to_shared(smem);

    const int tid  = threadIdx.x;
    const int lane = tid & 31;
    const int wid  = tid >> 5;
    const int g    = lane >> 2;       // 0..7
    const int tig  = lane & 3;        // 0..3
    const int wm   = wid >> 2;        // 0..1
    const int wn   = wid & 3;         // 0..3
    const int bm   = blockIdx.y * TBM;
    const int bn   = blockIdx.x * TBN;

    // precomputed fragment word offsets (per thread, fixed across ksteps)
    int abase[4][2], asw[4][2];   // [mt][0]: row m, [1]: row m+8
#pragma unroll
    for (int mt = 0; mt < 4; mt++) {
        int m0 = wm * 64 + mt * 16 + g;
        abase[mt][0] = m0 * 16 + tig;       asw[mt][0] = sw_of(m0);
        abase[mt][1] = (m0 + 8) * 16 + tig; asw[mt][1] = sw_of(m0 + 8);
    }
    int bbase[8], bsw[8];
#pragma unroll
    for (int nt = 0; nt < 8; nt++) {
        int n0 = wn * 64 + nt * 8 + g;
        bbase[nt] = n0 * 16 + tig; bsw[nt] = sw_of(n0);
    }

    float acc[4][8][4];
#pragma unroll
    for (int mt = 0; mt < 4; mt++)
#pragma unroll
        for (int nt = 0; nt < 8; nt++)
#pragma unroll
            for (int i = 0; i < 4; i++) acc[mt][nt][i] = 0.f;

    const int KT = K / TBK;

    // async loader: stage s <- k-tile kt
    auto load_stage = [&](int s, int kt) {
        const uint32_t base = smem_base + s * STAGE_BYTES;
        const int k0 = kt * TBK;
#pragma unroll
        for (int i = 0; i < 2; i++) {           // A: 512 chunks / 256 thr
            int c = tid + i * 256;
            int m = c >> 2, kc = c & 3;
            uint32_t dst = base + (uint32_t)(m * 64 + ((kc ^ sw_of(m)) << 4));
            const float* src = A + (size_t)(bm + m) * K + k0 + kc * 4;
            asm volatile("cp.async.cg.shared.global [%0], [%1], 16;" :: "r"(dst), "l"(src));
        }
#pragma unroll
        for (int i = 0; i < 4; i++) {           // B: 1024 chunks / 256 thr
            int c = tid + i * 256;
            int n = c >> 2, kc = c & 3;
            uint32_t dst = base + A_BYTES + (uint32_t)(n * 64 + ((kc ^ sw_of(n)) << 4));
            const float* src = B + (size_t)(bn + n) * K + k0 + kc * 4;
            asm volatile("cp.async.cg.shared.global [%0], [%1], 16;" :: "r"(dst), "l"(src));
        }
    };

    // prologue: fill 3 stages
#pragma unroll
    for (int s = 0; s < NSTAGE - 1; s++) {
        load_stage(s, s);
        asm volatile("cp.async.commit_group;");
    }

    for (int kt = 0; kt < KT; kt++) {
        const int s = kt & (NSTAGE - 1);
        asm volatile("cp.async.wait_group %0;" :: "n"(NSTAGE - 2));
        __syncthreads();

        const uint32_t* pa = smem + (size_t)s * (STAGE_BYTES / 4);
        const uint32_t* pb = pa + A_BYTES / 4;

#pragma unroll
        for (int ks = 0; ks < 2; ks++) {
            const int j0 = ks * 2;   // chunk index of kk ; kk = ks*8 + tig
            uint32_t af[4][4];
#pragma unroll
            for (int mt = 0; mt < 4; mt++) {
                af[mt][0] = pa[abase[mt][0] + ((j0 ^ asw[mt][0]) << 2)];
                af[mt][1] = pa[abase[mt][1] + ((j0 ^ asw[mt][1]) << 2)];
                af[mt][2] = pa[abase[mt][0] + (((j0 + 1) ^ asw[mt][0]) << 2)];
                af[mt][3] = pa[abase[mt][1] + (((j0 + 1) ^ asw[mt][1]) << 2)];
            }
            uint32_t bf[8][2];
#pragma unroll
            for (int nt = 0; nt < 8; nt++) {
                bf[nt][0] = pb[bbase[nt] + ((j0 ^ bsw[nt]) << 2)];
                bf[nt][1] = pb[bbase[nt] + (((j0 + 1) ^ bsw[nt]) << 2)];
            }
#pragma unroll
            for (int mt = 0; mt < 4; mt++)
#pragma unroll
                for (int nt = 0; nt < 8; nt++) {
                    asm volatile(
                        "mma.sync.aligned.m16n8k8.row.col.f32.tf32.tf32.f32 "
                        "{%0,%1,%2,%3}, {%4,%5,%6,%7}, {%8,%9}, {%0,%1,%2,%3};"
                        : "+f"(acc[mt][nt][0]), "+f"(acc[mt][nt][1]),
                          "+f"(acc[mt][nt][2]), "+f"(acc[mt][nt][3])
                        : "r"(af[mt][0]), "r"(af[mt][1]), "r"(af[mt][2]), "r"(af[mt][3]),
                          "r"(bf[nt][0]), "r"(bf[nt][1]));
                }
        }

        if (kt + NSTAGE - 1 < KT) load_stage((kt + NSTAGE - 1) & (NSTAGE - 1), kt + NSTAGE - 1);
        asm volatile("cp.async.commit_group;");
    }

    // epilogue
#pragma unroll
    for (int mt = 0; mt < 4; mt++) {
        int r0 = bm + wm * 64 + mt * 16 + g;
#pragma unroll
        for (int nt = 0; nt < 8; nt++) {
            int cc = bn + wn * 64 + nt * 8 + tig * 2;
            *(float2*)(C + (size_t)r0 * N + cc) = make_float2(acc[mt][nt][0], acc[mt][nt][1]);
            *(float2*)(C + (size_t)(r0 + 8) * N + cc) = make_float2(acc[mt][nt][2], acc[mt][nt][3]);
        }
    }
}

// ---------------- alpha projections ----------------------------------------
__global__ void alpha1_kernel(const float* __restrict__ h,
                              const float* __restrict__ a_src,
                              const float* __restrict__ a_dst)
{
    int n = blockIdx.x;
    int w = threadIdx.x >> 5, lane = threadIdx.x & 31;
    const float* row = h + (size_t)n * D1 + w * HID;
    float ss = 0.f, sd = 0.f;
#pragma unroll
    for (int o = lane; o < HID; o += 32) {
        float v = row[o];
        ss = fmaf(v, a_src[w * HID + o], ss);
        sd = fmaf(v, a_dst[w * HID + o], sd);
    }
#pragma unroll
    for (int off = 16; off; off >>= 1) {
        ss += __shfl_down_sync(0xffffffffu, ss, off);
        sd += __shfl_down_sync(0xffffffffu, sd, off);
    }
    if (lane == 0) { g_as1[n * H1 + w] = ss; g_ad1[n * H1 + w] = sd; }
}

__global__ void alpha2_kernel(const float* __restrict__ h,
                              const float* __restrict__ a_src,
                              const float* __restrict__ a_dst)
{
    int n = blockIdx.x;
    int w = threadIdx.x >> 5, lane = threadIdx.x & 31;
    const float* row = h + (size_t)n * D2 + w * OUT_DIM;
    float ss = 0.f, sd = 0.f;
#pragma unroll
    for (int o = lane; o < OUT_DIM; o += 32) {
        float v = row[o];
        ss = fmaf(v, a_src[w * OUT_DIM + o], ss);
        sd = fmaf(v, a_dst[w * OUT_DIM + o], sd);
    }
#pragma unroll
    for (int off = 16; off; off >>= 1) {
        ss += __shfl_down_sync(0xffffffffu, ss, off);
        sd += __shfl_down_sync(0xffffffffu, sd, off);
    }
    if (lane == 0) { g_as2[n * H2 + w] = ss; g_ad2[n * H2 + w] = sd; }
}

// ---------------- CSR build -------------------------------------------------
__global__ void hist_kernel(const int* __restrict__ ei) {
    int e = blockIdx.x * blockDim.x + threadIdx.x;
    if (e >= ET) return;
    int dst = (e < EE) ? ei[EE + e] : (e - EE);
    atomicAdd(&g_deg[dst], 1);
}

__global__ void scan_kernel() {
    __shared__ int sm[1024];
    __shared__ int carry;
    int t = threadIdx.x;
    if (t == 0) { carry = 0; g_rowptr[0] = 0; }
    __syncthreads();
    for (int base = 0; base < NN; base += 1024) {
        int i = base + t;
        int v = (i < NN) ? g_deg[i] : 0;
        sm[t] = v;
        __syncthreads();
        for (int off = 1; off < 1024; off <<= 1) {
            int add = (t >= off) ? sm[t - off] : 0;
            __syncthreads();
            sm[t] += add;
            __syncthreads();
        }
        if (i < NN) g_rowptr[i + 1] = sm[t] + carry;
        __syncthreads();
        if (t == 0) carry += sm[1023];
        __syncthreads();
    }
}

__global__ void scatter_kernel(const int* __restrict__ ei) {
    int e = blockIdx.x * blockDim.x + threadIdx.x;
    if (e >= ET) return;
    int src, dst;
    if (e < EE) { src = ei[e]; dst = ei[EE + e]; }
    else        { src = dst = e - EE; }
    int pos = g_rowptr[dst] + atomicAdd(&g_fill[dst], 1);
    g_csrc[pos] = src;
}

// ---------------- layer1 attention + aggregation (block per node, 256 thr) --
#define CH1 512
__global__ __launch_bounds__(256) void gat1_agg(
    const float* __restrict__ h, const float* __restrict__ b1,
    float* __restrict__ out)
{
    __shared__ float s_ex[CH1 * 4];
    __shared__ int   s_src[CH1];
    __shared__ float s_red[256 * 4];
    int n = blockIdx.x, tid = threadIdx.x;
    int row = g_rowptr[n];
    int deg = g_rowptr[n + 1] - row;
    float4 adv = *(const float4*)(g_ad1 + n * 4);

    float m0 = -1e30f, m1 = -1e30f, m2 = -1e30f, m3 = -1e30f;
    for (int j = tid; j < deg; j += 256) {
        int s = g_csrc[row + j];
        float4 a = *(const float4*)(g_as1 + s * 4);
        m0 = fmaxf(m0, lrelu(a.x + adv.x));
        m1 = fmaxf(m1, lrelu(a.y + adv.y));
        m2 = fmaxf(m2, lrelu(a.z + adv.z));
        m3 = fmaxf(m3, lrelu(a.w + adv.w));
    }
    s_red[tid] = m0; s_red[256 + tid] = m1; s_red[512 + tid] = m2; s_red[768 + tid] = m3;
    __syncthreads();
    for (int off = 128; off; off >>= 1) {
        if (tid < off) {
#pragma unroll
            for (int hh = 0; hh < 4; hh++)
                s_red[hh * 256 + tid] = fmaxf(s_red[hh * 256 + tid], s_red[hh * 256 + tid + off]);
        }
        __syncthreads();
    }
    m0 = s_red[0]; m1 = s_red[256]; m2 = s_red[512]; m3 = s_red[768];
    __syncthreads();

    float acc0 = 0.f, acc1 = 0.f, acc2 = 0.f, acc3 = 0.f;
    float d0 = 0.f, d1 = 0.f, d2 = 0.f, d3 = 0.f;
    for (int base = 0; base < deg; base += CH1) {
        int cnt = min(CH1, deg - base);
        for (int j = tid; j < cnt; j += 256) {
            int s = g_csrc[row + base + j];
            s_src[j] = s;
            float4 a = *(const float4*)(g_as1 + s * 4);
            float x0 = __expf(lrelu(a.x + adv.x) - m0);
            float x1 = __expf(lrelu(a.y + adv.y) - m1);
            float x2 = __expf(lrelu(a.z + adv.z) - m2);
            float x3 = __expf(lrelu(a.w + adv.w) - m3);
            s_ex[j * 4 + 0] = x0; s_ex[j * 4 + 1] = x1;
            s_ex[j * 4 + 2] = x2; s_ex[j * 4 + 3] = x3;
            d0 += x0; d1 += x1; d2 += x2; d3 += x3;
        }
        __syncthreads();
#pragma unroll 2
        for (int j = 0; j < cnt; j++) {
            int s = s_src[j];
            float4 xw = *(const float4*)(s_ex + j * 4);
            const float* hr = h + (size_t)s * D1 + tid;
            acc0 = fmaf(hr[0],   xw.x, acc0);
            acc1 = fmaf(hr[256], xw.y, acc1);
            acc2 = fmaf(hr[512], xw.z, acc2);
            acc3 = fmaf(hr[768], xw.w, acc3);
        }
        __syncthreads();
    }
    s_red[tid] = d0; s_red[256 + tid] = d1; s_red[512 + tid] = d2; s_red[768 + tid] = d3;
    __syncthreads();
    for (int off = 128; off; off >>= 1) {
        if (tid < off) {
#pragma unroll
            for (int hh = 0; hh < 4; hh++)
                s_red[hh * 256 + tid] += s_red[hh * 256 + tid + off];
        }
        __syncthreads();
    }
    float i0 = 1.f / (s_red[0] + 1e-16f);
    float i1 = 1.f / (s_red[256] + 1e-16f);
    float i2 = 1.f / (s_red[512] + 1e-16f);
    float i3 = 1.f / (s_red[768] + 1e-16f);

    // h1 feeds only GEMM2 -> store tf32-rounded (keeps cp.async GEMM exact)
    float* o = out + (size_t)n * D1;
    o[tid]       = tf32r(elu(acc0 * i0 + b1[tid]));
    o[256 + tid] = tf32r(elu(acc1 * i1 + b1[256 + tid]));
    o[512 + tid] = tf32r(elu(acc2 * i2 + b1[512 + tid]));
    o[768 + tid] = tf32r(elu(acc3 * i3 + b1[768 + tid]));
}

// ---------------- layer2 attention + aggregation (block per node, 128 thr) --
#define CH2 512
__global__ __launch_bounds__(128) void gat2_agg(
    const float* __restrict__ h, const float* __restrict__ b2,
    float* __restrict__ h2out)
{
    __shared__ float s_ex[CH2 * 2];
    __shared__ int   s_src[CH2];
    __shared__ float s_red[128 * 2];
    int n = blockIdx.x, tid = threadIdx.x;
    int row = g_rowptr[n];
    int deg = g_rowptr[n + 1] - row;
    float2 adv = *(const float2*)(g_ad2 + n * 2);

    float m0 = -1e30f, m1 = -1e30f;
    for (int j = tid; j < deg; j += 128) {
        int s = g_csrc[row + j];
        float2 a = *(const float2*)(g_as2 + s * 2);
        m0 = fmaxf(m0, lrelu(a.x + adv.x));
        m1 = fmaxf(m1, lrelu(a.y + adv.y));
    }
    s_red[tid] = m0; s_red[128 + tid] = m1;
    __syncthreads();
    for (int off = 64; off; off >>= 1) {
        if (tid < off) {
            s_red[tid] = fmaxf(s_red[tid], s_red[tid + off]);
            s_red[128 + tid] = fmaxf(s_red[128 + tid], s_red[128 + tid + off]);
        }
        __syncthreads();
    }
    m0 = s_red[0]; m1 = s_red[128];
    __syncthreads();

    float acc0 = 0.f, acc1 = 0.f, d0 = 0.f, d1 = 0.f;
    for (int base = 0; base < deg; base += CH2) {
        int cnt = min(CH2, deg - base);
        for (int j = tid; j < cnt; j += 128) {
            int s = g_csrc[row + base + j];
            s_src[j] = s;
            float2 a = *(const float2*)(g_as2 + s * 2);
            float x0 = __expf(lrelu(a.x + adv.x) - m0);
            float x1 = __expf(lrelu(a.y + adv.y) - m1);
            s_ex[j * 2 + 0] = x0; s_ex[j * 2 + 1] = x1;
            d0 += x0; d1 += x1;
        }
        __syncthreads();
#pragma unroll 2
        for (int j = 0; j < cnt; j++) {
            int s = s_src[j];
            float2 xw = *(const float2*)(s_ex + j * 2);
            const float* hr = h + (size_t)s * D2 + tid;
            acc0 = fmaf(hr[0],   xw.x, acc0);
            acc1 = fmaf(hr[128], xw.y, acc1);
        }
        __syncthreads();
    }
    s_red[tid] = d0; s_red[128 + tid] = d1;
    __syncthreads();
    for (int off = 64; off; off >>= 1) {
        if (tid < off) {
            s_red[tid] += s_red[tid + off];
            s_red[128 + tid] += s_red[128 + tid + off];
        }
        __syncthreads();
    }
    float i0 = 1.f / (s_red[0] + 1e-16f);
    float i1 = 1.f / (s_red[128] + 1e-16f);
    float o = (acc0 * i0 + acc1 * i1) * 0.5f + b2[tid];
    h2out[(size_t)n * OUT_DIM + tid] = elu(o);
}

// ---------------- pooling ---------------------------------------------------
__global__ void pool_kernel(const float* __restrict__ h2, const int* __restrict__ batch) {
    int n = blockIdx.x, t = threadIdx.x;
    int b = batch[n];
    atomicAdd(&g_pooled[b * OUT_DIM + t], h2[(size_t)n * OUT_DIM + t]);
    if (t == 0) atomicAdd(&g_cnt[b], 1);
}

// ---------------- proj + layernorm (block per graph, 768 threads) -----------
__global__ __launch_bounds__(768) void proj_ln_kernel(
    const float* __restrict__ W, const float* __restrict__ pb,
    const float* __restrict__ g, const float* __restrict__ beta,
    float* __restrict__ out)
{
    __shared__ float sp[OUT_DIM];
    __shared__ float red[768];
    int b = blockIdx.x, j = threadIdx.x;
    float c = (float)max(g_cnt[b], 1);
    if (j < OUT_DIM) sp[j] = g_pooled[b * OUT_DIM + j] / c;
    __syncthreads();
    float z = pb[j];
    const float* w = W + (size_t)j * OUT_DIM;
#pragma unroll 8
    for (int k = 0; k < OUT_DIM; k++) z = fmaf(sp[k], w[k], z);

    red[j] = z; __syncthreads();
    if (j < 256) red[j] += red[j + 512];
    __syncthreads();
    if (j < 256) red[j] += red[j + 256];
    __syncthreads();
    for (int off = 128; off; off >>= 1) { if (j < off) red[j] += red[j + off]; __syncthreads(); }
    float mean = red[0] / 768.f;
    __syncthreads();
    float dz = z - mean;
    red[j] = dz * dz; __syncthreads();
    if (j < 256) red[j] += red[j + 512];
    __syncthreads();
    if (j < 256) red[j] += red[j + 256];
    __syncthreads();
    for (int off = 128; off; off >>= 1) { if (j < off) red[j] += red[j + off]; __syncthreads(); }
    float var = red[0] / 768.f;
    out[(size_t)b * 768 + j] = dz * rsqrtf(var + LN_EPS) * g[j] + beta[j];
}

// ---------------- launch ----------------------------------------------------
extern "C" void kernel_launch(void* const* d_in, const int* in_sizes, int n_in,
                              void* d_out, int out_size)
{
    const float* x   = (const float*)d_in[0];
    const int*   ei  = (const int*)  d_in[1];
    const int*   bat = (const int*)  d_in[2];
    const float* W1  = (const float*)d_in[3];
    const float* a1s = (const float*)d_in[4];
    const float* a1d = (const float*)d_in[5];
    const float* b1  = (const float*)d_in[6];
    const float* W2  = (const float*)d_in[7];
    const float* a2s = (const float*)d_in[8];
    const float* a2d = (const float*)d_in[9];
    const float* b2  = (const float*)d_in[10];
    const float* pW  = (const float*)d_in[11];
    const float* pb  = (const float*)d_in[12];
    const float* lg  = (const float*)d_in[13];
    const float* lb  = (const float*)d_in[14];

    float* out = (float*)d_out;
    float* ge  = out;                 // (32, 768)
    float* h2  = out + BB * 768;      // (16000, 128)

    float *xr, *w1r, *w2r, *h1pre, *h1, *t2;
    cudaGetSymbolAddress((void**)&xr, g_xr);
    cudaGetSymbolAddress((void**)&w1r, g_w1r);
    cudaGetSymbolAddress((void**)&w2r, g_w2r);
    cudaGetSymbolAddress((void**)&h1pre, g_h1pre);
    cudaGetSymbolAddress((void**)&h1, g_h1);
    cudaGetSymbolAddress((void**)&t2, g_t2);

    cudaFuncSetAttribute(sgemm_tf32, cudaFuncAttributeMaxDynamicSharedMemorySize,
                         SMEM_BYTES);

    // launch order puts sgemm_tf32 (GEMM1) at submission slot 4 for ncu capture
    round_x_kernel<<<(NN * IN_DIM / 4 + 255) / 256, 256>>>(x);          // 1
    round_w_kernel<<<(D1 * IN_DIM / 4 + 255) / 256, 256>>>(W1, W2);     // 2
    zero_init_kernel<<<(NN + 255) / 256, 256>>>();                      // 3

    // layer 1 GEMM (16000 x 1024 x 768)                                // 4
    {
        dim3 grid(D1 / TBN, NN / TBM);   // (4, 125)
        sgemm_tf32<<<grid, 256, SMEM_BYTES>>>(xr, w1r, h1pre, NN, D1, IN_DIM);
    }

    // CSR build                                                         // 5-7
    hist_kernel<<<(ET + 255) / 256, 256>>>(ei);
    scan_kernel<<<1, 1024>>>();
    scatter_kernel<<<(ET + 255) / 256, 256>>>(ei);

    alpha1_kernel<<<NN, 128>>>(h1pre, a1s, a1d);                        // 8
    gat1_agg<<<NN, 256>>>(h1pre, b1, h1);                               // 9

    // layer 2 GEMM (16000 x 256 x 1024)                                // 10
    {
        dim3 grid(D2 / TBN, NN / TBM);   // (1, 125)
        sgemm_tf32<<<grid, 256, SMEM_BYTES>>>(h1, w2r, t2, NN, D2, D1);
    }
    alpha2_kernel<<<NN, 64>>>(t2, a2s, a2d);                            // 11
    gat2_agg<<<NN, 128>>>(t2, b2, h2);                                  // 12

    pool_kernel<<<NN, OUT_DIM>>>(h2, bat);                              // 13
    proj_ln_kernel<<<BB, 768>>>(pW, pb, lg, lb, ge);                    // 14
}

// round 4
// speedup vs baseline: 2.3014x; 1.0901x over previous
#include <cuda_runtime.h>
#include <cstdint>

#define NN 16000
#define EE 256000
#define ET 272000   // EE + NN self loops
#define BB 32
#define IN_DIM 768
#define HID 256
#define H1 4
#define OUT_DIM 128
#define H2 2
#define D1 (H1*HID)    // 1024
#define D2 (H2*OUT_DIM) // 256
#define LN_EPS 1e-5f

// ---------------- scratch (static device globals; no allocation allowed) ----
__device__ float g_xr[(size_t)NN * IN_DIM];  // tf32-rounded x
__device__ float g_w1r[D1 * IN_DIM];         // tf32-rounded W1
__device__ float g_w2r[D2 * D1];             // tf32-rounded W2
__device__ float g_h1pre[(size_t)NN * D1];   // layer1 GEMM out
__device__ float g_h1[(size_t)NN * D1];      // layer1 output (elu, tf32-rounded)
__device__ float g_t2[(size_t)NN * D2];      // layer2 GEMM out
__device__ float g_as1[NN * H1];
__device__ float g_ad1[NN * H1];
__device__ float g_as2[NN * H2];
__device__ float g_ad2[NN * H2];
__device__ int   g_deg[NN];
__device__ int   g_rowptr[NN + 1];
__device__ int   g_fill[NN];
__device__ int   g_csrc[ET];
__device__ float g_pooled[BB * OUT_DIM];
__device__ int   g_cnt[BB];

__device__ __forceinline__ float lrelu(float x) { return x > 0.f ? x : 0.2f * x; }
__device__ __forceinline__ float elu(float x) { return x > 0.f ? x : expm1f(x); }

__device__ __forceinline__ float tf32r(float f) {
    uint32_t o;
    asm("cvt.rna.tf32.f32 %0, %1;" : "=r"(o) : "f"(f));
    return __uint_as_float(o);
}

// ---------------- fused prep: round x/W1/W2 + zero counters -----------------
__global__ void prep_kernel(const float* __restrict__ x,
                            const float* __restrict__ W1,
                            const float* __restrict__ W2)
{
    int i = blockIdx.x * blockDim.x + threadIdx.x;
    const int nx = NN * IN_DIM / 4;
    const int n1 = D1 * IN_DIM / 4;
    const int n2 = D2 * D1 / 4;
    if (i < nx) {
        float4 v = ((const float4*)x)[i];
        v.x = tf32r(v.x); v.y = tf32r(v.y); v.z = tf32r(v.z); v.w = tf32r(v.w);
        ((float4*)g_xr)[i] = v;
    }
    if (i < n1) {
        float4 v = ((const float4*)W1)[i];
        v.x = tf32r(v.x); v.y = tf32r(v.y); v.z = tf32r(v.z); v.w = tf32r(v.w);
        ((float4*)g_w1r)[i] = v;
    }
    if (i < n2) {
        float4 v = ((const float4*)W2)[i];
        v.x = tf32r(v.x); v.y = tf32r(v.y); v.z = tf32r(v.z); v.w = tf32r(v.w);
        ((float4*)g_w2r)[i] = v;
    }
    if (i < NN) { g_deg[i] = 0; g_fill[i] = 0; }
    if (i < BB * OUT_DIM) g_pooled[i] = 0.f;
    if (i < BB) g_cnt[i] = 0;
}

// ---------------- TF32 tensor-core GEMM (cp.async 4-stage, 2 CTA/SM) --------
// C[M,N] = A[M,K] * B[N,K]^T ; A,B row-major, already tf32-rounded.
// Block tile 128x128x16, 8 warps of 64x32, 2 CTAs per SM.
#define TBM 128
#define TBN 128
#define TBK 16
#define A_BYTES (TBM * 64)
#define B_BYTES (TBN * 64)
#define STAGE_BYTES (A_BYTES + B_BYTES)   // 16384
#define NSTAGE 4
#define SMEM_BYTES (NSTAGE * STAGE_BYTES) // 65536

__device__ __forceinline__ int sw_of(int r) { return (r ^ (r >> 2)) & 3; }

__global__ __launch_bounds__(256, 2) void sgemm_tf32(
    const float* __restrict__ A, const float* __restrict__ B,
    float* __restrict__ C, int M, int N, int K)
{
    extern __shared__ uint32_t smem[];
    const uint32_t smem_base = (uint32_t)__cvta_generic_to_shared(smem);

    const int tid  = threadIdx.x;
    const int lane = tid & 31;
    const int wid  = tid >> 5;
    const int g    = lane >> 2;       // 0..7
    const int tig  = lane & 3;        // 0..3
    const int wm   = wid >> 2;        // 0..1 -> warp M origin wm*64
    const int wn   = wid & 3;         // 0..3 -> warp N origin wn*32
    const int bm   = blockIdx.y * TBM;
    const int bn   = blockIdx.x * TBN;

    float acc[4][4][4];
#pragma unroll
    for (int mt = 0; mt < 4; mt++)
#pragma unroll
        for (int nt = 0; nt < 4; nt++)
#pragma unroll
            for (int i = 0; i < 4; i++) acc[mt][nt][i] = 0.f;

    const int KT = K / TBK;

    // async loader: stage s <- k-tile kt (A: 512 chunks, B: 512 chunks)
    auto load_stage = [&](int s, int kt) {
        const uint32_t base = smem_base + s * STAGE_BYTES;
        const int k0 = kt * TBK;
        {
            int m = tid >> 2, kc = tid & 3;
            uint32_t dst = base + (uint32_t)(m * 64 + ((kc ^ sw_of(m)) << 4));
            const float* src = A + (size_t)(bm + m) * K + k0 + kc * 4;
            asm volatile("cp.async.cg.shared.global [%0], [%1], 16;" :: "r"(dst), "l"(src));
            int c2 = tid + 256;
            int m2 = c2 >> 2, kc2 = c2 & 3;
            uint32_t dst2 = base + (uint32_t)(m2 * 64 + ((kc2 ^ sw_of(m2)) << 4));
            const float* src2 = A + (size_t)(bm + m2) * K + k0 + kc2 * 4;
            asm volatile("cp.async.cg.shared.global [%0], [%1], 16;" :: "r"(dst2), "l"(src2));
        }
        {
            int n = tid >> 2, kc = tid & 3;
            uint32_t dst = base + A_BYTES + (uint32_t)(n * 64 + ((kc ^ sw_of(n)) << 4));
            const float* src = B + (size_t)(bn + n) * K + k0 + kc * 4;
            asm volatile("cp.async.cg.shared.global [%0], [%1], 16;" :: "r"(dst), "l"(src));
            int c2 = tid + 256;
            int n2 = c2 >> 2, kc2 = c2 & 3;
            uint32_t dst2 = base + A_BYTES + (uint32_t)(n2 * 64 + ((kc2 ^ sw_of(n2)) << 4));
            const float* src2 = B + (size_t)(bn + n2) * K + k0 + kc2 * 4;
            asm volatile("cp.async.cg.shared.global [%0], [%1], 16;" :: "r"(dst2), "l"(src2));
        }
    };

#pragma unroll
    for (int s = 0; s < NSTAGE - 1; s++) {
        load_stage(s, s);
        asm volatile("cp.async.commit_group;");
    }

    for (int kt = 0; kt < KT; kt++) {
        const int s = kt & (NSTAGE - 1);
        asm volatile("cp.async.wait_group %0;" :: "n"(NSTAGE - 2));
        __syncthreads();

        const uint32_t* pa = smem + (size_t)s * (STAGE_BYTES / 4);
        const uint32_t* pb = pa + A_BYTES / 4;

#pragma unroll
        for (int ks = 0; ks < 2; ks++) {
            const int j0 = ks * 2;   // 16B-chunk index of kk ; kk = ks*8 + tig
            uint32_t af[4][4];
#pragma unroll
            for (int mt = 0; mt < 4; mt++) {
                int m0 = wm * 64 + mt * 16 + g;
                int s0 = sw_of(m0), s1 = sw_of(m0 + 8);
                af[mt][0] = pa[m0 * 16 + tig + ((j0 ^ s0) << 2)];
                af[mt][1] = pa[(m0 + 8) * 16 + tig + ((j0 ^ s1) << 2)];
                af[mt][2] = pa[m0 * 16 + tig + (((j0 + 1) ^ s0) << 2)];
                af[mt][3] = pa[(m0 + 8) * 16 + tig + (((j0 + 1) ^ s1) << 2)];
            }
            uint32_t bf[4][2];
#pragma unroll
            for (int nt = 0; nt < 4; nt++) {
                int n0 = wn * 32 + nt * 8 + g;
                int s0 = sw_of(n0);
                bf[nt][0] = pb[n0 * 16 + tig + ((j0 ^ s0) << 2)];
                bf[nt][1] = pb[n0 * 16 + tig + (((j0 + 1) ^ s0) << 2)];
            }
#pragma unroll
            for (int mt = 0; mt < 4; mt++)
#pragma unroll
                for (int nt = 0; nt < 4; nt++) {
                    asm volatile(
                        "mma.sync.aligned.m16n8k8.row.col.f32.tf32.tf32.f32 "
                        "{%0,%1,%2,%3}, {%4,%5,%6,%7}, {%8,%9}, {%0,%1,%2,%3};"
                        : "+f"(acc[mt][nt][0]), "+f"(acc[mt][nt][1]),
                          "+f"(acc[mt][nt][2]), "+f"(acc[mt][nt][3])
                        : "r"(af[mt][0]), "r"(af[mt][1]), "r"(af[mt][2]), "r"(af[mt][3]),
                          "r"(bf[nt][0]), "r"(bf[nt][1]));
                }
        }

        if (kt + NSTAGE - 1 < KT) load_stage((kt + NSTAGE - 1) & (NSTAGE - 1), kt + NSTAGE - 1);
        asm volatile("cp.async.commit_group;");
    }

    // epilogue
#pragma unroll
    for (int mt = 0; mt < 4; mt++) {
        int r0 = bm + wm * 64 + mt * 16 + g;
#pragma unroll
        for (int nt = 0; nt < 4; nt++) {
            int cc = bn + wn * 32 + nt * 8 + tig * 2;
            *(float2*)(C + (size_t)r0 * N + cc) = make_float2(acc[mt][nt][0], acc[mt][nt][1]);
            *(float2*)(C + (size_t)(r0 + 8) * N + cc) = make_float2(acc[mt][nt][2], acc[mt][nt][3]);
        }
    }
}

// ---------------- alpha projections ----------------------------------------
__global__ void alpha1_kernel(const float* __restrict__ h,
                              const float* __restrict__ a_src,
                              const float* __restrict__ a_dst)
{
    int n = blockIdx.x;
    int w = threadIdx.x >> 5, lane = threadIdx.x & 31;
    const float* row = h + (size_t)n * D1 + w * HID;
    float ss = 0.f, sd = 0.f;
#pragma unroll
    for (int o = lane; o < HID; o += 32) {
        float v = row[o];
        ss = fmaf(v, a_src[w * HID + o], ss);
        sd = fmaf(v, a_dst[w * HID + o], sd);
    }
#pragma unroll
    for (int off = 16; off; off >>= 1) {
        ss += __shfl_down_sync(0xffffffffu, ss, off);
        sd += __shfl_down_sync(0xffffffffu, sd, off);
    }
    if (lane == 0) { g_as1[n * H1 + w] = ss; g_ad1[n * H1 + w] = sd; }
}

__global__ void alpha2_kernel(const float* __restrict__ h,
                              const float* __restrict__ a_src,
                              const float* __restrict__ a_dst)
{
    int n = blockIdx.x;
    int w = threadIdx.x >> 5, lane = threadIdx.x & 31;
    const float* row = h + (size_t)n * D2 + w * OUT_DIM;
    float ss = 0.f, sd = 0.f;
#pragma unroll
    for (int o = lane; o < OUT_DIM; o += 32) {
        float v = row[o];
        ss = fmaf(v, a_src[w * OUT_DIM + o], ss);
        sd = fmaf(v, a_dst[w * OUT_DIM + o], sd);
    }
#pragma unroll
    for (int off = 16; off; off >>= 1) {
        ss += __shfl_down_sync(0xffffffffu, ss, off);
        sd += __shfl_down_sync(0xffffffffu, sd, off);
    }
    if (lane == 0) { g_as2[n * H2 + w] = ss; g_ad2[n * H2 + w] = sd; }
}

// ---------------- CSR build -------------------------------------------------
__global__ void hist_kernel(const int* __restrict__ ei) {
    int e = blockIdx.x * blockDim.x + threadIdx.x;
    if (e >= ET) return;
    int dst = (e < EE) ? ei[EE + e] : (e - EE);
    atomicAdd(&g_deg[dst], 1);
}

__global__ void scan_kernel() {
    __shared__ int sm[1024];
    __shared__ int carry;
    int t = threadIdx.x;
    if (t == 0) { carry = 0; g_rowptr[0] = 0; }
    __syncthreads();
    for (int base = 0; base < NN; base += 1024) {
        int i = base + t;
        int v = (i < NN) ? g_deg[i] : 0;
        sm[t] = v;
        __syncthreads();
        for (int off = 1; off < 1024; off <<= 1) {
            int add = (t >= off) ? sm[t - off] : 0;
            __syncthreads();
            sm[t] += add;
            __syncthreads();
        }
        if (i < NN) g_rowptr[i + 1] = sm[t] + carry;
        __syncthreads();
        if (t == 0) carry += sm[1023];
        __syncthreads();
    }
}

__global__ void scatter_kernel(const int* __restrict__ ei) {
    int e = blockIdx.x * blockDim.x + threadIdx.x;
    if (e >= ET) return;
    int src, dst;
    if (e < EE) { src = ei[e]; dst = ei[EE + e]; }
    else        { src = dst = e - EE; }
    int pos = g_rowptr[dst] + atomicAdd(&g_fill[dst], 1);
    g_csrc[pos] = src;
}

// ---------------- layer1 attention + aggregation (block per node, 256 thr) --
// thread -> (head = tid>>6, 4 consecutive features) : one LDG.128 per edge
#define CH1 512
__global__ __launch_bounds__(256) void gat1_agg(
    const float* __restrict__ h, const float* __restrict__ b1,
    float* __restrict__ out)
{
    __shared__ float s_ex[CH1 * 4];
    __shared__ int   s_src[CH1];
    __shared__ float s_red[256 * 4];
    int n = blockIdx.x, tid = threadIdx.x;
    int row = g_rowptr[n];
    int deg = g_rowptr[n + 1] - row;
    float4 adv = *(const float4*)(g_ad1 + n * 4);

    const int head = tid >> 6;          // 0..3
    const int off  = (tid & 63) << 2;   // 0..252

    // pass A: per-head max
    float m0 = -1e30f, m1 = -1e30f, m2 = -1e30f, m3 = -1e30f;
    for (int j = tid; j < deg; j += 256) {
        int s = g_csrc[row + j];
        float4 a = *(const float4*)(g_as1 + s * 4);
        m0 = fmaxf(m0, lrelu(a.x + adv.x));
        m1 = fmaxf(m1, lrelu(a.y + adv.y));
        m2 = fmaxf(m2, lrelu(a.z + adv.z));
        m3 = fmaxf(m3, lrelu(a.w + adv.w));
    }
    s_red[tid] = m0; s_red[256 + tid] = m1; s_red[512 + tid] = m2; s_red[768 + tid] = m3;
    __syncthreads();
    for (int o = 128; o; o >>= 1) {
        if (tid < o) {
#pragma unroll
            for (int hh = 0; hh < 4; hh++)
                s_red[hh * 256 + tid] = fmaxf(s_red[hh * 256 + tid], s_red[hh * 256 + tid + o]);
        }
        __syncthreads();
    }
    m0 = s_red[0]; m1 = s_red[256]; m2 = s_red[512]; m3 = s_red[768];
    __syncthreads();

    // pass B: exp-weighted accumulation
    float4 acc = make_float4(0.f, 0.f, 0.f, 0.f);
    float d0 = 0.f, d1 = 0.f, d2 = 0.f, d3 = 0.f;
    const float* hb = h + head * 256 + off;
    for (int base = 0; base < deg; base += CH1) {
        int cnt = min(CH1, deg - base);
        for (int j = tid; j < cnt; j += 256) {
            int s = g_csrc[row + base + j];
            s_src[j] = s;
            float4 a = *(const float4*)(g_as1 + s * 4);
            float x0 = __expf(lrelu(a.x + adv.x) - m0);
            float x1 = __expf(lrelu(a.y + adv.y) - m1);
            float x2 = __expf(lrelu(a.z + adv.z) - m2);
            float x3 = __expf(lrelu(a.w + adv.w) - m3);
            s_ex[j * 4 + 0] = x0; s_ex[j * 4 + 1] = x1;
            s_ex[j * 4 + 2] = x2; s_ex[j * 4 + 3] = x3;
            d0 += x0; d1 += x1; d2 += x2; d3 += x3;
        }
        __syncthreads();
#pragma unroll 4
        for (int j = 0; j < cnt; j++) {
            int s = s_src[j];
            float w = s_ex[j * 4 + head];
            float4 v = *(const float4*)(hb + (size_t)s * D1);
            acc.x = fmaf(v.x, w, acc.x);
            acc.y = fmaf(v.y, w, acc.y);
            acc.z = fmaf(v.z, w, acc.z);
            acc.w = fmaf(v.w, w, acc.w);
        }
        __syncthreads();
    }
    s_red[tid] = d0; s_red[256 + tid] = d1; s_red[512 + tid] = d2; s_red[768 + tid] = d3;
    __syncthreads();
    for (int o = 128; o; o >>= 1) {
        if (tid < o) {
#pragma unroll
            for (int hh = 0; hh < 4; hh++)
                s_red[hh * 256 + tid] += s_red[hh * 256 + tid + o];
        }
        __syncthreads();
    }
    float inv = 1.f / (s_red[head * 256] + 1e-16f);

    float4 bv = *(const float4*)(b1 + head * 256 + off);
    float4 o4;
    o4.x = tf32r(elu(acc.x * inv + bv.x));
    o4.y = tf32r(elu(acc.y * inv + bv.y));
    o4.z = tf32r(elu(acc.z * inv + bv.z));
    o4.w = tf32r(elu(acc.w * inv + bv.w));
    *(float4*)(out + (size_t)n * D1 + head * 256 + off) = o4;
}

// ---------------- layer2 attention + aggregation (block per node, 128 thr) --
#define CH2 512
__global__ __launch_bounds__(128) void gat2_agg(
    const float* __restrict__ h, const float* __restrict__ b2,
    float* __restrict__ h2out)
{
    __shared__ float s_ex[CH2 * 2];
    __shared__ int   s_src[CH2];
    __shared__ float s_red[128 * 2];
    __shared__ float s_comb[128];
    int n = blockIdx.x, tid = threadIdx.x;
    int row = g_rowptr[n];
    int deg = g_rowptr[n + 1] - row;
    float2 adv = *(const float2*)(g_ad2 + n * 2);

    const int head = tid >> 6;          // 0..1
    const int foff = (tid & 63) << 1;   // 0..126

    float m0 = -1e30f, m1 = -1e30f;
    for (int j = tid; j < deg; j += 128) {
        int s = g_csrc[row + j];
        float2 a = *(const float2*)(g_as2 + s * 2);
        m0 = fmaxf(m0, lrelu(a.x + adv.x));
        m1 = fmaxf(m1, lrelu(a.y + adv.y));
    }
    s_red[tid] = m0; s_red[128 + tid] = m1;
    __syncthreads();
    for (int o = 64; o; o >>= 1) {
        if (tid < o) {
            s_red[tid] = fmaxf(s_red[tid], s_red[tid + o]);
            s_red[128 + tid] = fmaxf(s_red[128 + tid], s_red[128 + tid + o]);
        }
        __syncthreads();
    }
    m0 = s_red[0]; m1 = s_red[128];
    __syncthreads();

    float2 acc = make_float2(0.f, 0.f);
    float d0 = 0.f, d1 = 0.f;
    const float* hb = h + head * OUT_DIM + foff;
    for (int base = 0; base < deg; base += CH2) {
        int cnt = min(CH2, deg - base);
        for (int j = tid; j < cnt; j += 128) {
            int s = g_csrc[row + base + j];
            s_src[j] = s;
            float2 a = *(const float2*)(g_as2 + s * 2);
            float x0 = __expf(lrelu(a.x + adv.x) - m0);
            float x1 = __expf(lrelu(a.y + adv.y) - m1);
            s_ex[j * 2 + 0] = x0; s_ex[j * 2 + 1] = x1;
            d0 += x0; d1 += x1;
        }
        __syncthreads();
#pragma unroll 4
        for (int j = 0; j < cnt; j++) {
            int s = s_src[j];
            float w = s_ex[j * 2 + head];
            float2 v = *(const float2*)(hb + (size_t)s * D2);
            acc.x = fmaf(v.x, w, acc.x);
            acc.y = fmaf(v.y, w, acc.y);
        }
        __syncthreads();
    }
    s_red[tid] = d0; s_red[128 + tid] = d1;
    __syncthreads();
    for (int o = 64; o; o >>= 1) {
        if (tid < o) {
            s_red[tid] += s_red[tid + o];
            s_red[128 + tid] += s_red[128 + tid + o];
        }
        __syncthreads();
    }
    float inv = 1.f / (s_red[head * 128] + 1e-16f);
    float2 val = make_float2(acc.x * inv, acc.y * inv);

    if (head == 1) { s_comb[foff] = val.x; s_comb[foff + 1] = val.y; }
    __syncthreads();
    if (head == 0) {
        float ox = (val.x + s_comb[foff]) * 0.5f + b2[foff];
        float oy = (val.y + s_comb[foff + 1]) * 0.5f + b2[foff + 1];
        *(float2*)(h2out + (size_t)n * OUT_DIM + foff) = make_float2(elu(ox), elu(oy));
    }
}

// ---------------- pooling ---------------------------------------------------
__global__ void pool_kernel(const float* __restrict__ h2, const int* __restrict__ batch) {
    int n = blockIdx.x, t = threadIdx.x;
    int b = batch[n];
    atomicAdd(&g_pooled[b * OUT_DIM + t], h2[(size_t)n * OUT_DIM + t]);
    if (t == 0) atomicAdd(&g_cnt[b], 1);
}

// ---------------- proj + layernorm (block per graph, 768 threads) -----------
__global__ __launch_bounds__(768) void proj_ln_kernel(
    const float* __restrict__ W, const float* __restrict__ pb,
    const float* __restrict__ g, const float* __restrict__ beta,
    float* __restrict__ out)
{
    __shared__ float sp[OUT_DIM];
    __shared__ float red[768];
    int b = blockIdx.x, j = threadIdx.x;
    float c = (float)max(g_cnt[b], 1);
    if (j < OUT_DIM) sp[j] = g_pooled[b * OUT_DIM + j] / c;
    __syncthreads();
    float z = pb[j];
    const float* w = W + (size_t)j * OUT_DIM;
#pragma unroll 8
    for (int k = 0; k < OUT_DIM; k++) z = fmaf(sp[k], w[k], z);

    red[j] = z; __syncthreads();
    if (j < 256) red[j] += red[j + 512];
    __syncthreads();
    if (j < 256) red[j] += red[j + 256];
    __syncthreads();
    for (int off = 128; off; off >>= 1) { if (j < off) red[j] += red[j + off]; __syncthreads(); }
    float mean = red[0] / 768.f;
    __syncthreads();
    float dz = z - mean;
    red[j] = dz * dz; __syncthreads();
    if (j < 256) red[j] += red[j + 512];
    __syncthreads();
    if (j < 256) red[j] += red[j + 256];
    __syncthreads();
    for (int off = 128; off; off >>= 1) { if (j < off) red[j] += red[j + off]; __syncthreads(); }
    float var = red[0] / 768.f;
    out[(size_t)b * 768 + j] = dz * rsqrtf(var + LN_EPS) * g[j] + beta[j];
}

// ---------------- launch ----------------------------------------------------
extern "C" void kernel_launch(void* const* d_in, const int* in_sizes, int n_in,
                              void* d_out, int out_size)
{
    const float* x   = (const float*)d_in[0];
    const int*   ei  = (const int*)  d_in[1];
    const int*   bat = (const int*)  d_in[2];
    const float* W1  = (const float*)d_in[3];
    const float* a1s = (const float*)d_in[4];
    const float* a1d = (const float*)d_in[5];
    const float* b1  = (const float*)d_in[6];
    const float* W2  = (const float*)d_in[7];
    const float* a2s = (const float*)d_in[8];
    const float* a2d = (const float*)d_in[9];
    const float* b2  = (const float*)d_in[10];
    const float* pW  = (const float*)d_in[11];
    const float* pb  = (const float*)d_in[12];
    const float* lg  = (const float*)d_in[13];
    const float* lb  = (const float*)d_in[14];

    float* out = (float*)d_out;
    float* ge  = out;                 // (32, 768)
    float* h2  = out + BB * 768;      // (16000, 128)

    float *xr, *w1r, *w2r, *h1pre, *h1, *t2;
    cudaGetSymbolAddress((void**)&xr, g_xr);
    cudaGetSymbolAddress((void**)&w1r, g_w1r);
    cudaGetSymbolAddress((void**)&w2r, g_w2r);
    cudaGetSymbolAddress((void**)&h1pre, g_h1pre);
    cudaGetSymbolAddress((void**)&h1, g_h1);
    cudaGetSymbolAddress((void**)&t2, g_t2);

    cudaFuncSetAttribute(sgemm_tf32, cudaFuncAttributeMaxDynamicSharedMemorySize,
                         SMEM_BYTES);

    // slot 4 = sgemm_tf32 (GEMM1) for ncu capture
    prep_kernel<<<(NN * IN_DIM / 4 + 255) / 256, 256>>>(x, W1, W2);     // 1
    hist_kernel<<<(ET + 255) / 256, 256>>>(ei);                         // 2
    scan_kernel<<<1, 1024>>>();                                         // 3
    {
        dim3 grid(D1 / TBN, NN / TBM);   // (8, 125)                    // 4
        sgemm_tf32<<<grid, 256, SMEM_BYTES>>>(xr, w1r, h1pre, NN, D1, IN_DIM);
    }
    scatter_kernel<<<(ET + 255) / 256, 256>>>(ei);                      // 5
    alpha1_kernel<<<NN, 128>>>(h1pre, a1s, a1d);                        // 6
    gat1_agg<<<NN, 256>>>(h1pre, b1, h1);                               // 7
    {
        dim3 grid(D2 / TBN, NN / TBM);   // (2, 125)                    // 8
        sgemm_tf32<<<grid, 256, SMEM_BYTES>>>(h1, w2r, t2, NN, D2, D1);
    }
    alpha2_kernel<<<NN, 64>>>(t2, a2s, a2d);                            // 9
    gat2_agg<<<NN, 128>>>(t2, b2, h2);                                  // 10
    pool_kernel<<<NN, OUT_DIM>>>(h2, bat);                              // 11
    proj_ln_kernel<<<BB, 768>>>(pW, pb, lg, lb, ge);                    // 12
}

// round 6
// speedup vs baseline: 2.4056x; 1.0453x over previous
#include <cuda_runtime.h>
#include <cstdint>

#define NN 16000
#define EE 256000
#define ET 272000   // EE + NN self loops
#define BB 32
#define IN_DIM 768
#define HID 256
#define H1 4
#define OUT_DIM 128
#define H2 2
#define D1 (H1*HID)    // 1024
#define D2 (H2*OUT_DIM) // 256
#define LN_EPS 1e-5f

// ---------------- scratch (static device globals; no allocation allowed) ----
__device__ float g_xr[(size_t)NN * IN_DIM];  // tf32-rounded x
__device__ float g_w1r[D1 * IN_DIM];         // tf32-rounded W1
__device__ float g_w2r[D2 * D1];             // tf32-rounded W2
__device__ float g_h1pre[(size_t)NN * D1];   // layer1 GEMM out
__device__ float g_h1[(size_t)NN * D1];      // layer1 output (elu, tf32-rounded)
__device__ float g_t2[(size_t)NN * D2];      // layer2 GEMM out
__device__ float g_as1[NN * H1];
__device__ float g_ad1[NN * H1];
__device__ float g_as2[NN * H2];
__device__ float g_ad2[NN * H2];
__device__ int   g_deg[NN];
__device__ int   g_rowptr[NN + 1];
__device__ int   g_fill[NN];
__device__ int   g_csrc[ET];
__device__ float g_pooled[BB * OUT_DIM];
__device__ int   g_cnt[BB];

__device__ __forceinline__ float lrelu(float x) { return x > 0.f ? x : 0.2f * x; }
__device__ __forceinline__ float elu(float x) { return x > 0.f ? x : expm1f(x); }

__device__ __forceinline__ float tf32r(float f) {
    uint32_t o;
    asm("cvt.rna.tf32.f32 %0, %1;" : "=r"(o) : "f"(f));
    return __uint_as_float(o);
}

// ---------------- fused prep: round x/W1/W2 + zero counters -----------------
__global__ void prep_kernel(const float* __restrict__ x,
                            const float* __restrict__ W1,
                            const float* __restrict__ W2)
{
    int i = blockIdx.x * blockDim.x + threadIdx.x;
    const int nx = NN * IN_DIM / 4;
    const int n1 = D1 * IN_DIM / 4;
    const int n2 = D2 * D1 / 4;
    if (i < nx) {
        float4 v = ((const float4*)x)[i];
        v.x = tf32r(v.x); v.y = tf32r(v.y); v.z = tf32r(v.z); v.w = tf32r(v.w);
        ((float4*)g_xr)[i] = v;
    }
    if (i < n1) {
        float4 v = ((const float4*)W1)[i];
        v.x = tf32r(v.x); v.y = tf32r(v.y); v.z = tf32r(v.z); v.w = tf32r(v.w);
        ((float4*)g_w1r)[i] = v;
    }
    if (i < n2) {
        float4 v = ((const float4*)W2)[i];
        v.x = tf32r(v.x); v.y = tf32r(v.y); v.z = tf32r(v.z); v.w = tf32r(v.w);
        ((float4*)g_w2r)[i] = v;
    }
    if (i < NN) { g_deg[i] = 0; g_fill[i] = 0; }
    if (i < BB * OUT_DIM) g_pooled[i] = 0.f;
    if (i < BB) g_cnt[i] = 0;
}

// ---------------- TF32 tensor-core GEMM (cp.async + ldmatrix) ---------------
// C[M,N] = A[M,K] * B[N,K]^T ; A,B row-major, already tf32-rounded.
// Block tile 128x128x16, 8 warps of 64x32, 2 CTAs per SM, 4-stage cp.async.
#define TBM 128
#define TBN 128
#define TBK 16
#define A_BYTES (TBM * 64)
#define B_BYTES (TBN * 64)
#define STAGE_BYTES (A_BYTES + B_BYTES)   // 16384
#define NSTAGE 4
#define SMEM_BYTES (NSTAGE * STAGE_BYTES) // 65536

__device__ __forceinline__ int sw_of(int r) { return (r ^ (r >> 2)) & 3; }

__global__ __launch_bounds__(256, 2) void sgemm_tf32(
    const float* __restrict__ A, const float* __restrict__ B,
    float* __restrict__ C, int M, int N, int K)
{
    extern __shared__ uint32_t smem[];
    const uint32_t smem_base = (uint32_t)__cvta_generic_to_shared(smem);

    const int tid  = threadIdx.x;
    const int lane = tid & 31;
    const int wid  = tid >> 5;
    const int g    = lane >> 2;       // 0..7
    const int tig  = lane & 3;        // 0..3
    const int wm   = wid >> 2;        // 0..1 -> warp M origin wm*64
    const int wn   = wid & 3;         // 0..3 -> warp N origin wn*32
    const int bm   = blockIdx.y * TBM;
    const int bn   = blockIdx.x * TBN;

    // ldmatrix per-lane row/chunk roles
    const int rlA = (lane & 7) + ((lane >> 3) & 1) * 8; // row within 16-row A tile
    const int caA = lane >> 4;                          // +chunk for matrices 2,3
    const int rlB = lane & 7;                           // row within 8-row B tile
    const int cbB = (lane >> 3) & 1;                    // +chunk for matrix 1

    // per-mt / per-nt byte offsets + swizzle constants
    uint32_t aoff[4]; int aswz[4];
#pragma unroll
    for (int mt = 0; mt < 4; mt++) {
        int r = wm * 64 + mt * 16 + rlA;
        aoff[mt] = (uint32_t)(r * 64);
        aswz[mt] = sw_of(r);
    }
    uint32_t boff[4]; int bswz[4];
#pragma unroll
    for (int nt = 0; nt < 4; nt++) {
        int r = wn * 32 + nt * 8 + rlB;
        boff[nt] = (uint32_t)(A_BYTES + r * 64);
        bswz[nt] = sw_of(r);
    }

    float acc[4][4][4];
#pragma unroll
    for (int mt = 0; mt < 4; mt++)
#pragma unroll
        for (int nt = 0; nt < 4; nt++)
#pragma unroll
            for (int i = 0; i < 4; i++) acc[mt][nt][i] = 0.f;

    const int KT = K / TBK;

    auto load_stage = [&](int s, int kt) {
        const uint32_t base = smem_base + s * STAGE_BYTES;
        const int k0 = kt * TBK;
        {
            int m = tid >> 2, kc = tid & 3;
            uint32_t dst = base + (uint32_t)(m * 64 + ((kc ^ sw_of(m)) << 4));
            const float* src = A + (size_t)(bm + m) * K + k0 + kc * 4;
            asm volatile("cp.async.cg.shared.global [%0], [%1], 16;" :: "r"(dst), "l"(src));
            int c2 = tid + 256;
            int m2 = c2 >> 2, kc2 = c2 & 3;
            uint32_t dst2 = base + (uint32_t)(m2 * 64 + ((kc2 ^ sw_of(m2)) << 4));
            const float* src2 = A + (size_t)(bm + m2) * K + k0 + kc2 * 4;
            asm volatile("cp.async.cg.shared.global [%0], [%1], 16;" :: "r"(dst2), "l"(src2));
        }
        {
            int n = tid >> 2, kc = tid & 3;
            uint32_t dst = base + A_BYTES + (uint32_t)(n * 64 + ((kc ^ sw_of(n)) << 4));
            const float* src = B + (size_t)(bn + n) * K + k0 + kc * 4;
            asm volatile("cp.async.cg.shared.global [%0], [%1], 16;" :: "r"(dst), "l"(src));
            int c2 = tid + 256;
            int n2 = c2 >> 2, kc2 = c2 & 3;
            uint32_t dst2 = base + A_BYTES + (uint32_t)(n2 * 64 + ((kc2 ^ sw_of(n2)) << 4));
            const float* src2 = B + (size_t)(bn + n2) * K + k0 + kc2 * 4;
            asm volatile("cp.async.cg.shared.global [%0], [%1], 16;" :: "r"(dst2), "l"(src2));
        }
    };

#pragma unroll
    for (int s = 0; s < NSTAGE - 1; s++) {
        load_stage(s, s);
        asm volatile("cp.async.commit_group;");
    }

    for (int kt = 0; kt < KT; kt++) {
        const int s = kt & (NSTAGE - 1);
        asm volatile("cp.async.wait_group %0;" :: "n"(NSTAGE - 2));
        __syncthreads();

        const uint32_t base = smem_base + s * STAGE_BYTES;

#pragma unroll
        for (int ks = 0; ks < 2; ks++) {
            const int j0 = ks * 2;
            uint32_t af[4][4];
#pragma unroll
            for (int mt = 0; mt < 4; mt++) {
                uint32_t addr = base + aoff[mt] + (uint32_t)((((j0 + caA) ^ aswz[mt])) << 4);
                asm volatile("ldmatrix.sync.aligned.m8n8.x4.shared.b16 {%0,%1,%2,%3}, [%4];"
                    : "=r"(af[mt][0]), "=r"(af[mt][1]), "=r"(af[mt][2]), "=r"(af[mt][3])
                    : "r"(addr));
            }
            uint32_t bf[4][2];
#pragma unroll
            for (int nt = 0; nt < 4; nt++) {
                uint32_t addr = base + boff[nt] + (uint32_t)((((j0 + cbB) ^ bswz[nt])) << 4);
                asm volatile("ldmatrix.sync.aligned.m8n8.x2.shared.b16 {%0,%1}, [%2];"
                    : "=r"(bf[nt][0]), "=r"(bf[nt][1])
                    : "r"(addr));
            }
#pragma unroll
            for (int mt = 0; mt < 4; mt++)
#pragma unroll
                for (int nt = 0; nt < 4; nt++) {
                    asm volatile(
                        "mma.sync.aligned.m16n8k8.row.col.f32.tf32.tf32.f32 "
                        "{%0,%1,%2,%3}, {%4,%5,%6,%7}, {%8,%9}, {%0,%1,%2,%3};"
                        : "+f"(acc[mt][nt][0]), "+f"(acc[mt][nt][1]),
                          "+f"(acc[mt][nt][2]), "+f"(acc[mt][nt][3])
                        : "r"(af[mt][0]), "r"(af[mt][1]), "r"(af[mt][2]), "r"(af[mt][3]),
                          "r"(bf[nt][0]), "r"(bf[nt][1]));
                }
        }

        if (kt + NSTAGE - 1 < KT) load_stage((kt + NSTAGE - 1) & (NSTAGE - 1), kt + NSTAGE - 1);
        asm volatile("cp.async.commit_group;");
    }

    // epilogue
#pragma unroll
    for (int mt = 0; mt < 4; mt++) {
        int r0 = bm + wm * 64 + mt * 16 + g;
#pragma unroll
        for (int nt = 0; nt < 4; nt++) {
            int cc = bn + wn * 32 + nt * 8 + tig * 2;
            *(float2*)(C + (size_t)r0 * N + cc) = make_float2(acc[mt][nt][0], acc[mt][nt][1]);
            *(float2*)(C + (size_t)(r0 + 8) * N + cc) = make_float2(acc[mt][nt][2], acc[mt][nt][3]);
        }
    }
}

// ---------------- alpha projections ----------------------------------------
__global__ void alpha1_kernel(const float* __restrict__ h,
                              const float* __restrict__ a_src,
                              const float* __restrict__ a_dst)
{
    int n = blockIdx.x;
    int w = threadIdx.x >> 5, lane = threadIdx.x & 31;
    const float* row = h + (size_t)n * D1 + w * HID;
    float ss = 0.f, sd = 0.f;
#pragma unroll
    for (int o = lane; o < HID; o += 32) {
        float v = row[o];
        ss = fmaf(v, a_src[w * HID + o], ss);
        sd = fmaf(v, a_dst[w * HID + o], sd);
    }
#pragma unroll
    for (int off = 16; off; off >>= 1) {
        ss += __shfl_down_sync(0xffffffffu, ss, off);
        sd += __shfl_down_sync(0xffffffffu, sd, off);
    }
    if (lane == 0) { g_as1[n * H1 + w] = ss; g_ad1[n * H1 + w] = sd; }
}

__global__ void alpha2_kernel(const float* __restrict__ h,
                              const float* __restrict__ a_src,
                              const float* __restrict__ a_dst)
{
    int n = blockIdx.x;
    int w = threadIdx.x >> 5, lane = threadIdx.x & 31;
    const float* row = h + (size_t)n * D2 + w * OUT_DIM;
    float ss = 0.f, sd = 0.f;
#pragma unroll
    for (int o = lane; o < OUT_DIM; o += 32) {
        float v = row[o];
        ss = fmaf(v, a_src[w * OUT_DIM + o], ss);
        sd = fmaf(v, a_dst[w * OUT_DIM + o], sd);
    }
#pragma unroll
    for (int off = 16; off; off >>= 1) {
        ss += __shfl_down_sync(0xffffffffu, ss, off);
        sd += __shfl_down_sync(0xffffffffu, sd, off);
    }
    if (lane == 0) { g_as2[n * H2 + w] = ss; g_ad2[n * H2 + w] = sd; }
}

// ---------------- CSR build -------------------------------------------------
__global__ void hist_kernel(const int* __restrict__ ei) {
    int e = blockIdx.x * blockDim.x + threadIdx.x;
    if (e >= ET) return;
    int dst = (e < EE) ? ei[EE + e] : (e - EE);
    atomicAdd(&g_deg[dst], 1);
}

// warp-shuffle based scan (1024 threads, 3 barriers per chunk)
__global__ void scan_kernel() {
    __shared__ int warp_sums[32];
    __shared__ int carry_s;
    int t = threadIdx.x, lane = t & 31, w = t >> 5;
    if (t == 0) { carry_s = 0; g_rowptr[0] = 0; }
    __syncthreads();
    for (int base = 0; base < NN; base += 1024) {
        int i = base + t;
        int x = (i < NN) ? g_deg[i] : 0;
#pragma unroll
        for (int o = 1; o < 32; o <<= 1) {
            int y = __shfl_up_sync(0xffffffffu, x, o);
            if (lane >= o) x += y;
        }
        if (lane == 31) warp_sums[w] = x;
        __syncthreads();
        if (w == 0) {
            int s = warp_sums[lane];
#pragma unroll
            for (int o = 1; o < 32; o <<= 1) {
                int y = __shfl_up_sync(0xffffffffu, s, o);
                if (lane >= o) s += y;
            }
            warp_sums[lane] = s;
        }
        __syncthreads();
        int pre = (w > 0 ? warp_sums[w - 1] : 0) + carry_s;
        if (i < NN) g_rowptr[i + 1] = x + pre;
        __syncthreads();
        if (t == 0) carry_s += warp_sums[31];
        __syncthreads();
    }
}

__global__ void scatter_kernel(const int* __restrict__ ei) {
    int e = blockIdx.x * blockDim.x + threadIdx.x;
    if (e >= ET) return;
    int src, dst;
    if (e < EE) { src = ei[e]; dst = ei[EE + e]; }
    else        { src = dst = e - EE; }
    int pos = g_rowptr[dst] + atomicAdd(&g_fill[dst], 1);
    g_csrc[pos] = src;
}

// ---------------- layer1 attention + aggregation (block per node, 256 thr) --
#define CH1 512
__global__ __launch_bounds__(256) void gat1_agg(
    const float* __restrict__ h, const float* __restrict__ b1,
    float* __restrict__ out)
{
    __shared__ float s_ex[CH1 * 4];
    __shared__ int   s_src[CH1];
    __shared__ float s_red[256 * 4];
    int n = blockIdx.x, tid = threadIdx.x;
    int row = g_rowptr[n];
    int deg = g_rowptr[n + 1] - row;
    float4 adv = *(const float4*)(g_ad1 + n * 4);

    const int head = tid >> 6;          // 0..3
    const int off  = (tid & 63) << 2;   // 0..252

    float m0 = -1e30f, m1 = -1e30f, m2 = -1e30f, m3 = -1e30f;
    for (int j = tid; j < deg; j += 256) {
        int s = g_csrc[row + j];
        float4 a = *(const float4*)(g_as1 + s * 4);
        m0 = fmaxf(m0, lrelu(a.x + adv.x));
        m1 = fmaxf(m1, lrelu(a.y + adv.y));
        m2 = fmaxf(m2, lrelu(a.z + adv.z));
        m3 = fmaxf(m3, lrelu(a.w + adv.w));
    }
    s_red[tid] = m0; s_red[256 + tid] = m1; s_red[512 + tid] = m2; s_red[768 + tid] = m3;
    __syncthreads();
    for (int o = 128; o; o >>= 1) {
        if (tid < o) {
#pragma unroll
            for (int hh = 0; hh < 4; hh++)
                s_red[hh * 256 + tid] = fmaxf(s_red[hh * 256 + tid], s_red[hh * 256 + tid + o]);
        }
        __syncthreads();
    }
    m0 = s_red[0]; m1 = s_red[256]; m2 = s_red[512]; m3 = s_red[768];
    __syncthreads();

    float4 acc = make_float4(0.f, 0.f, 0.f, 0.f);
    float d0 = 0.f, d1 = 0.f, d2 = 0.f, d3 = 0.f;
    const float* hb = h + head * 256 + off;
    for (int base = 0; base < deg; base += CH1) {
        int cnt = min(CH1, deg - base);
        for (int j = tid; j < cnt; j += 256) {
            int s = g_csrc[row + base + j];
            s_src[j] = s;
            float4 a = *(const float4*)(g_as1 + s * 4);
            float x0 = __expf(lrelu(a.x + adv.x) - m0);
            float x1 = __expf(lrelu(a.y + adv.y) - m1);
            float x2 = __expf(lrelu(a.z + adv.z) - m2);
            float x3 = __expf(lrelu(a.w + adv.w) - m3);
            s_ex[j * 4 + 0] = x0; s_ex[j * 4 + 1] = x1;
            s_ex[j * 4 + 2] = x2; s_ex[j * 4 + 3] = x3;
            d0 += x0; d1 += x1; d2 += x2; d3 += x3;
        }
        __syncthreads();
#pragma unroll 4
        for (int j = 0; j < cnt; j++) {
            int s = s_src[j];
            float w = s_ex[j * 4 + head];
            float4 v = *(const float4*)(hb + (size_t)s * D1);
            acc.x = fmaf(v.x, w, acc.x);
            acc.y = fmaf(v.y, w, acc.y);
            acc.z = fmaf(v.z, w, acc.z);
            acc.w = fmaf(v.w, w, acc.w);
        }
        __syncthreads();
    }
    s_red[tid] = d0; s_red[256 + tid] = d1; s_red[512 + tid] = d2; s_red[768 + tid] = d3;
    __syncthreads();
    for (int o = 128; o; o >>= 1) {
        if (tid < o) {
#pragma unroll
            for (int hh = 0; hh < 4; hh++)
                s_red[hh * 256 + tid] += s_red[hh * 256 + tid + o];
        }
        __syncthreads();
    }
    float inv = 1.f / (s_red[head * 256] + 1e-16f);

    float4 bv = *(const float4*)(b1 + head * 256 + off);
    float4 o4;
    o4.x = tf32r(elu(acc.x * inv + bv.x));
    o4.y = tf32r(elu(acc.y * inv + bv.y));
    o4.z = tf32r(elu(acc.z * inv + bv.z));
    o4.w = tf32r(elu(acc.w * inv + bv.w));
    *(float4*)(out + (size_t)n * D1 + head * 256 + off) = o4;
}

// ---------------- layer2 attention + aggregation (block per node, 128 thr) --
#define CH2 512
__global__ __launch_bounds__(128) void gat2_agg(
    const float* __restrict__ h, const float* __restrict__ b2,
    float* __restrict__ h2out)
{
    __shared__ float s_ex[CH2 * 2];
    __shared__ int   s_src[CH2];
    __shared__ float s_red[128 * 2];
    __shared__ float s_comb[128];
    int n = blockIdx.x, tid = threadIdx.x;
    int row = g_rowptr[n];
    int deg = g_rowptr[n + 1] - row;
    float2 adv = *(const float2*)(g_ad2 + n * 2);

    const int head = tid >> 6;          // 0..1
    const int foff = (tid & 63) << 1;   // 0..126

    float m0 = -1e30f, m1 = -1e30f;
    for (int j = tid; j < deg; j += 128) {
        int s = g_csrc[row + j];
        float2 a = *(const float2*)(g_as2 + s * 2);
        m0 = fmaxf(m0, lrelu(a.x + adv.x));
        m1 = fmaxf(m1, lrelu(a.y + adv.y));
    }
    s_red[tid] = m0; s_red[128 + tid] = m1;
    __syncthreads();
    for (int o = 64; o; o >>= 1) {
        if (tid < o) {
            s_red[tid] = fmaxf(s_red[tid], s_red[tid + o]);
            s_red[128 + tid] = fmaxf(s_red[128 + tid], s_red[128 + tid + o]);
        }
        __syncthreads();
    }
    m0 = s_red[0]; m1 = s_red[128];
    __syncthreads();

    float2 acc = make_float2(0.f, 0.f);
    float d0 = 0.f, d1 = 0.f;
    const float* hb = h + head * OUT_DIM + foff;
    for (int base = 0; base < deg; base += CH2) {
        int cnt = min(CH2, deg - base);
        for (int j = tid; j < cnt; j += 128) {
            int s = g_csrc[row + base + j];
            s_src[j] = s;
            float2 a = *(const float2*)(g_as2 + s * 2);
            float x0 = __expf(lrelu(a.x + adv.x) - m0);
            float x1 = __expf(lrelu(a.y + adv.y) - m1);
            s_ex[j * 2 + 0] = x0; s_ex[j * 2 + 1] = x1;
            d0 += x0; d1 += x1;
        }
        __syncthreads();
#pragma unroll 4
        for (int j = 0; j < cnt; j++) {
            int s = s_src[j];
            float w = s_ex[j * 2 + head];
            float2 v = *(const float2*)(hb + (size_t)s * D2);
            acc.x = fmaf(v.x, w, acc.x);
            acc.y = fmaf(v.y, w, acc.y);
        }
        __syncthreads();
    }
    s_red[tid] = d0; s_red[128 + tid] = d1;
    __syncthreads();
    for (int o = 64; o; o >>= 1) {
        if (tid < o) {
            s_red[tid] += s_red[tid + o];
            s_red[128 + tid] += s_red[128 + tid + o];
        }
        __syncthreads();
    }
    float inv = 1.f / (s_red[head * 128] + 1e-16f);
    float2 val = make_float2(acc.x * inv, acc.y * inv);

    if (head == 1) { s_comb[foff] = val.x; s_comb[foff + 1] = val.y; }
    __syncthreads();
    if (head == 0) {
        float ox = (val.x + s_comb[foff]) * 0.5f + b2[foff];
        float oy = (val.y + s_comb[foff + 1]) * 0.5f + b2[foff + 1];
        *(float2*)(h2out + (size_t)n * OUT_DIM + foff) = make_float2(elu(ox), elu(oy));
    }
}

// ---------------- pooling (run-length on sorted batch, 125 blocks) ----------
__global__ __launch_bounds__(128) void pool_kernel(
    const float* __restrict__ h2, const int* __restrict__ batch)
{
    __shared__ int s_b[128];
    int blk = blockIdx.x, f = threadIdx.x;
    int n0 = blk * 128;
    s_b[f] = batch[n0 + f];
    __syncthreads();

    float acc = 0.f;
    int cur = s_b[0];
    int cnt = 0;
#pragma unroll 4
    for (int j = 0; j < 128; j++) {
        int b = s_b[j];
        if (b != cur) {
            atomicAdd(&g_pooled[cur * OUT_DIM + f], acc);
            if (f == 0) atomicAdd(&g_cnt[cur], cnt);
            acc = 0.f; cnt = 0; cur = b;
        }
        acc += h2[(size_t)(n0 + j) * OUT_DIM + f];
        cnt++;
    }
    atomicAdd(&g_pooled[cur * OUT_DIM + f], acc);
    if (f == 0) atomicAdd(&g_cnt[cur], cnt);
}

// ---------------- proj + layernorm (block per graph, 768 threads) -----------
__global__ __launch_bounds__(768) void proj_ln_kernel(
    const float* __restrict__ W, const float* __restrict__ pb,
    const float* __restrict__ g, const float* __restrict__ beta,
    float* __restrict__ out)
{
    __shared__ float sp[OUT_DIM];
    __shared__ float red[768];
    int b = blockIdx.x, j = threadIdx.x;
    float c = (float)max(g_cnt[b], 1);
    if (j < OUT_DIM) sp[j] = g_pooled[b * OUT_DIM + j] / c;
    __syncthreads();
    float z = pb[j];
    const float* w = W + (size_t)j * OUT_DIM;
#pragma unroll 8
    for (int k = 0; k < OUT_DIM; k++) z = fmaf(sp[k], w[k], z);

    red[j] = z; __syncthreads();
    if (j < 256) red[j] += red[j + 512];
    __syncthreads();
    if (j < 256) red[j] += red[j + 256];
    __syncthreads();
    for (int off = 128; off; off >>= 1) { if (j < off) red[j] += red[j + off]; __syncthreads(); }
    float mean = red[0] / 768.f;
    __syncthreads();
    float dz = z - mean;
    red[j] = dz * dz; __syncthreads();
    if (j < 256) red[j] += red[j + 512];
    __syncthreads();
    if (j < 256) red[j] += red[j + 256];
    __syncthreads();
    for (int off = 128; off; off >>= 1) { if (j < off) red[j] += red[j + off]; __syncthreads(); }
    float var = red[0] / 768.f;
    out[(size_t)b * 768 + j] = dz * rsqrtf(var + LN_EPS) * g[j] + beta[j];
}

// ---------------- launch ----------------------------------------------------
extern "C" void kernel_launch(void* const* d_in, const int* in_sizes, int n_in,
                              void* d_out, int out_size)
{
    const float* x   = (const float*)d_in[0];
    const int*   ei  = (const int*)  d_in[1];
    const int*   bat = (const int*)  d_in[2];
    const float* W1  = (const float*)d_in[3];
    const float* a1s = (const float*)d_in[4];
    const float* a1d = (const float*)d_in[5];
    const float* b1  = (const float*)d_in[6];
    const float* W2  = (const float*)d_in[7];
    const float* a2s = (const float*)d_in[8];
    const float* a2d = (const float*)d_in[9];
    const float* b2  = (const float*)d_in[10];
    const float* pW  = (const float*)d_in[11];
    const float* pb  = (const float*)d_in[12];
    const float* lg  = (const float*)d_in[13];
    const float* lb  = (const float*)d_in[14];

    float* out = (float*)d_out;
    float* ge  = out;                 // (32, 768)
    float* h2  = out + BB * 768;      // (16000, 128)

    float *xr, *w1r, *w2r, *h1pre, *h1, *t2;
    cudaGetSymbolAddress((void**)&xr, g_xr);
    cudaGetSymbolAddress((void**)&w1r, g_w1r);
    cudaGetSymbolAddress((void**)&w2r, g_w2r);
    cudaGetSymbolAddress((void**)&h1pre, g_h1pre);
    cudaGetSymbolAddress((void**)&h1, g_h1);
    cudaGetSymbolAddress((void**)&t2, g_t2);

    cudaFuncSetAttribute(sgemm_tf32, cudaFuncAttributeMaxDynamicSharedMemorySize,
                         SMEM_BYTES);

    // slot 4 = sgemm_tf32 (GEMM1) for ncu capture
    prep_kernel<<<(NN * IN_DIM / 4 + 255) / 256, 256>>>(x, W1, W2);     // 1
    hist_kernel<<<(ET + 255) / 256, 256>>>(ei);                         // 2
    scan_kernel<<<1, 1024>>>();                                         // 3
    {
        dim3 grid(D1 / TBN, NN / TBM);   // (8, 125)                    // 4
        sgemm_tf32<<<grid, 256, SMEM_BYTES>>>(xr, w1r, h1pre, NN, D1, IN_DIM);
    }
    scatter_kernel<<<(ET + 255) / 256, 256>>>(ei);                      // 5
    alpha1_kernel<<<NN, 128>>>(h1pre, a1s, a1d);                        // 6
    gat1_agg<<<NN, 256>>>(h1pre, b1, h1);                               // 7
    {
        dim3 grid(D2 / TBN, NN / TBM);   // (2, 125)                    // 8
        sgemm_tf32<<<grid, 256, SMEM_BYTES>>>(h1, w2r, t2, NN, D2, D1);
    }
    alpha2_kernel<<<NN, 64>>>(t2, a2s, a2d);                            // 9
    gat2_agg<<<NN, 128>>>(t2, b2, h2);                                  // 10
    pool_kernel<<<NN / 128, 128>>>(h2, bat);                            // 11
    proj_ln_kernel<<<BB, 768>>>(pW, pb, lg, lb, ge);                    // 12
}